// round 14
// baseline (speedup 1.0000x reference)
#include <cuda_runtime.h>
#include <cuda_bf16.h>
#include <math.h>

#define NN 50000
#define EE 500000
#define GG 256
#define DD 64
#define LL 3
#define NT_EDGE ((EE + 127) / 128)

// ------------------------------------------------------------------ globals
__device__ float    g_h[NN * DD];
__device__ unsigned g_ea[(size_t)EE * 32];      // bf16x2 words
__device__ unsigned g_Arh[NN * 32];             // bf16x2 gather tables
__device__ unsigned g_Ach[NN * 32];
__device__ unsigned g_Brh[NN * 32];
__device__ float    g_hnew[NN * DD];
__device__ double   g_stats[2 * DD];
__device__ float    g_ab[2 * DD];
__device__ float    g_pool[GG * DD];
__device__ float    g_cnt[GG];
__device__ float    g_cf[GG * 16];

__device__ unsigned g_wbond[64 * 36];           // hi-only
__device__ unsigned g_wpre[LL][192 * 36];       // hi-only
__device__ unsigned g_wehi[LL][4][64 * 36];     // hi-only
__device__ unsigned g_watom[2][64 * 68];        // hi+lo (fp32 output path)
__device__ float    g_bpre[LL][192];

__device__ __forceinline__ float sp_f(float x) {
    return x > 15.f ? x : __logf(1.f + __expf(x));
}
__device__ __forceinline__ int clampi(int v, int hi) {
    return v < 0 ? 0 : (v >= hi ? hi - 1 : v);
}
__device__ __forceinline__ unsigned pack2(float x, float y) {
    __nv_bfloat162 h = __floats2bfloat162_rn(x, y);
    return *reinterpret_cast<unsigned*>(&h);
}
__device__ __forceinline__ float2 up2(unsigned u) {
    __nv_bfloat162 h = *reinterpret_cast<__nv_bfloat162*>(&u);
    return __bfloat1622float2(h);
}
__device__ __forceinline__ void red2(float* a, float x, float y) {
    asm volatile("red.global.add.v2.f32 [%0], {%1,%2};" :: "l"(a), "f"(x), "f"(y) : "memory");
}
__device__ __forceinline__ void mma_bf16(float& c0, float& c1, float& c2, float& c3,
                                         unsigned a0, unsigned a1, unsigned a2, unsigned a3,
                                         unsigned b0, unsigned b1) {
    asm volatile("mma.sync.aligned.m16n8k16.row.col.f32.bf16.bf16.f32 "
                 "{%0,%1,%2,%3}, {%4,%5,%6,%7}, {%8,%9}, {%0,%1,%2,%3};\n"
                 : "+f"(c0), "+f"(c1), "+f"(c2), "+f"(c3)
                 : "r"(a0), "r"(a1), "r"(a2), "r"(a3), "r"(b0), "r"(b1));
}

// hi+lo split-weight version (embed_nodes only)
template<int K0, int NT, int LD>
__device__ __forceinline__ void mma_tiles(const unsigned* sA, const unsigned* sWhi,
                                          const unsigned* sWlo, float acc[][NT][4],
                                          int wm, int wcol0, int gid, int tig) {
#pragma unroll
    for (int k0 = 0; k0 < K0; k0++) {
        unsigned a[2][4];
#pragma unroll
        for (int mt = 0; mt < 2; mt++) {
            const unsigned* base = &sA[(wm * 32 + mt * 16 + gid) * LD + k0 * 8 + tig];
            a[mt][0] = base[0];
            a[mt][1] = base[8 * LD];
            a[mt][2] = base[4];
            a[mt][3] = base[8 * LD + 4];
        }
#pragma unroll
        for (int nt = 0; nt < NT; nt++) {
            int off = (wcol0 + nt * 8 + gid) * LD + k0 * 8 + tig;
            unsigned bh0 = sWhi[off], bh1 = sWhi[off + 4];
            unsigned bl0 = sWlo[off], bl1 = sWlo[off + 4];
#pragma unroll
            for (int mt = 0; mt < 2; mt++) {
                mma_bf16(acc[mt][nt][0], acc[mt][nt][1], acc[mt][nt][2], acc[mt][nt][3],
                         a[mt][0], a[mt][1], a[mt][2], a[mt][3], bh0, bh1);
                mma_bf16(acc[mt][nt][0], acc[mt][nt][1], acc[mt][nt][2], acc[mt][nt][3],
                         a[mt][0], a[mt][1], a[mt][2], a[mt][3], bl0, bl1);
            }
        }
    }
}

// hi-only version
template<int K0, int NT, int LD>
__device__ __forceinline__ void mma_tiles_hi(const unsigned* sA, const unsigned* sWhi,
                                             float acc[][NT][4],
                                             int wm, int wcol0, int gid, int tig) {
#pragma unroll
    for (int k0 = 0; k0 < K0; k0++) {
        unsigned a[2][4];
#pragma unroll
        for (int mt = 0; mt < 2; mt++) {
            const unsigned* base = &sA[(wm * 32 + mt * 16 + gid) * LD + k0 * 8 + tig];
            a[mt][0] = base[0];
            a[mt][1] = base[8 * LD];
            a[mt][2] = base[4];
            a[mt][3] = base[8 * LD + 4];
        }
#pragma unroll
        for (int nt = 0; nt < NT; nt++) {
            int off = (wcol0 + nt * 8 + gid) * LD + k0 * 8 + tig;
            unsigned bh0 = sWhi[off], bh1 = sWhi[off + 4];
#pragma unroll
            for (int mt = 0; mt < 2; mt++)
                mma_bf16(acc[mt][nt][0], acc[mt][nt][1], acc[mt][nt][2], acc[mt][nt][3],
                         a[mt][0], a[mt][1], a[mt][2], a[mt][3], bh0, bh1);
        }
    }
}

// ------------------------------------------------------------------ one-time weight conversion
__global__ void k_cvt_all(const float* eu_W1, const float* eu_b1,
                          const float* nu_W1, const float* nu_b1,
                          const float* eu_W2, const float* nu_W2,
                          const float* W_bond, const float* W_atom) {
    int b = blockIdx.x, tid = threadIdx.x;
    if (b == 22) {   // W_atom: hi+lo
        __nv_bfloat16* hhi = reinterpret_cast<__nv_bfloat16*>(g_watom[0]);
        __nv_bfloat16* hlo = reinterpret_cast<__nv_bfloat16*>(g_watom[1]);
        for (int idx = tid; idx < 112 * 64; idx += 256) {
            int k = idx >> 6, n = idx & 63;
            float w = (k < 108) ? W_atom[k * 64 + n] : 0.f;
            __nv_bfloat16 hi = __float2bfloat16(w);
            float lo = w - __bfloat162float(hi);
            hhi[(size_t)n * 136 + k] = hi;
            hlo[(size_t)n * 136 + k] = __float2bfloat16(lo);
        }
        return;
    }
    const float* src; int i = 0, ncoff = 0, validK = 64;
    unsigned* dhi = 0;
    if (b == 0) {
        src = W_bond; validK = 41;
        dhi = g_wbond;
        for (int idx = tid; idx < LL * 192; idx += 256) {
            int ii = idx / 192, n = idx % 192;
            float v = 0.f;
            if (n < 64)        v = eu_b1[ii * 64 + n];
            else if (n >= 128) v = nu_b1[ii * 64 + (n - 128)];
            g_bpre[ii][n] = v;
        }
    } else {
        i = (b - 1) / 7; int j = (b - 1) % 7;
        const float* euW1 = eu_W1 + (size_t)i * 12288;
        const float* nuW1 = nu_W1 + (size_t)i * 8192;
        switch (j) {
            case 0: src = euW1;            dhi = g_wpre[i]; ncoff = 0;   break;
            case 1: src = euW1 + 4096;     dhi = g_wpre[i]; ncoff = 64;  break;
            case 2: src = nuW1;            dhi = g_wpre[i]; ncoff = 128; break;
            case 3: src = euW1 + 8192;     dhi = g_wehi[i][0]; break;
            case 4: src = eu_W2 + (size_t)i * 4096; dhi = g_wehi[i][1]; break;
            case 5: src = nuW1 + 4096;     dhi = g_wehi[i][2]; break;
            default: src = nu_W2 + (size_t)i * 4096; dhi = g_wehi[i][3]; break;
        }
    }
    __nv_bfloat16* hhi = reinterpret_cast<__nv_bfloat16*>(dhi);
    for (int idx = tid; idx < 4096; idx += 256) {
        int k = idx >> 6, n = idx & 63;
        float w = (k < validK) ? src[k * 64 + n] : 0.f;
        hhi[(size_t)(n + ncoff) * 72 + k] = __float2bfloat16(w);
    }
}

// ------------------------------------------------------------------ small kernels
__global__ void k_charge(const float* charge, const float* Wc, const float* bc) {
    int i = blockIdx.x * 256 + threadIdx.x;
    if (i < GG * 16) g_cf[i] = charge[i >> 4] * Wc[i & 15] + bc[i & 15];
    if (i < GG * DD) g_pool[i] = 0.f;
    if (i < GG) g_cnt[i] = 0.f;
}

// ------------------------------------------------------------------ node embedding via MMA (K=112)
__global__ __launch_bounds__(256) void k_embed_nodes_mma(
    const float* x, const int* batch, const float* b) {
    extern __shared__ unsigned dyn[];
    unsigned* sA = dyn;
    unsigned* sW = dyn + 128 * 68;
    int tid = threadIdx.x, n0 = blockIdx.x * 128;
    int warp = tid >> 5, lane = tid & 31;
    int wm = warp >> 1, wn = warp & 1;
    int gid = lane >> 2, tig = lane & 3;

    {
        const uint4* src = reinterpret_cast<const uint4*>(g_watom[0]);
        uint4* dst = reinterpret_cast<uint4*>(sW);
        for (int idx = tid; idx < 2 * 64 * 68 / 4; idx += 256) dst[idx] = src[idx];
    }
    for (int idx = tid; idx < 128 * 56; idx += 256) {
        int nr = idx / 56, kw = idx - nr * 56;
        int n = n0 + nr; if (n >= NN) n = NN - 1;
        int k = kw * 2;
        float v0, v1;
        int bb = clampi(batch[n], GG);
        v0 = (k < 92)      ? x[(size_t)n * 92 + k]
           : (k < 108)     ? g_cf[bb * 16 + (k - 92)] : 0.f;
        int k1 = k + 1;
        v1 = (k1 < 92)     ? x[(size_t)n * 92 + k1]
           : (k1 < 108)    ? g_cf[bb * 16 + (k1 - 92)] : 0.f;
        sA[nr * 68 + kw] = pack2(v0, v1);
    }
    __syncthreads();

    float acc[2][4][4];
#pragma unroll
    for (int mt = 0; mt < 2; mt++)
#pragma unroll
        for (int nt = 0; nt < 4; nt++) {
            float2 bv = *reinterpret_cast<const float2*>(&b[wn * 32 + nt * 8 + tig * 2]);
            acc[mt][nt][0] = bv.x; acc[mt][nt][1] = bv.y;
            acc[mt][nt][2] = bv.x; acc[mt][nt][3] = bv.y;
        }
    mma_tiles<7, 4, 68>(sA, sW, sW + 64 * 68, acc, wm, wn * 32, gid, tig);
#pragma unroll
    for (int mt = 0; mt < 2; mt++)
#pragma unroll
        for (int nt = 0; nt < 4; nt++) {
            int row = wm * 32 + mt * 16 + gid;
            int col = wn * 32 + nt * 8 + tig * 2;
            int n = n0 + row;
            if (n < NN)
                *reinterpret_cast<float2*>(&g_h[(size_t)n * 64 + col]) =
                    make_float2(acc[mt][nt][0], acc[mt][nt][1]);
            if (n + 8 < NN)
                *reinterpret_cast<float2*>(&g_h[(size_t)(n + 8) * 64 + col]) =
                    make_float2(acc[mt][nt][2], acc[mt][nt][3]);
        }
}

// ------------------------------------------------------------------ edge embedding (hi-only)
__global__ __launch_bounds__(256) void k_embed_edges_mma(const float* ea, const float* b) {
    extern __shared__ float dynf[];
    float*    flat = dynf;                               // 128*41
    unsigned* sA   = reinterpret_cast<unsigned*>(dynf + 5248);
    unsigned* sW   = sA + 128 * 36;                      // 64*36 hi only
    int tid = threadIdx.x, e0 = blockIdx.x * 128;
    int warp = tid >> 5, lane = tid & 31;
    int wm = warp >> 1, wn = warp & 1;
    int gid = lane >> 2, tig = lane & 3;

    {
        const uint4* src = reinterpret_cast<const uint4*>(g_wbond);
        uint4* dst = reinterpret_cast<uint4*>(sW);
        for (int idx = tid; idx < 64 * 36 / 4; idx += 256) dst[idx] = src[idx];
    }
    int valid = EE - e0; if (valid > 128) valid = 128;
    int nload = valid * 41;
    for (int idx = tid; idx < nload; idx += 256)
        flat[idx] = ea[(size_t)e0 * 41 + idx];
    __syncthreads();
    for (int idx = tid; idx < 128 * 24; idx += 256) {
        int er = idx / 24, kw = idx - er * 24;
        int k = kw * 2;
        float v0 = 0.f, v1 = 0.f;
        if (er < valid) {
            if (k < 41)     v0 = flat[er * 41 + k];
            if (k + 1 < 41) v1 = flat[er * 41 + k + 1];
        }
        sA[er * 36 + kw] = pack2(v0, v1);
    }
    __syncthreads();

    float acc[2][4][4];
#pragma unroll
    for (int mt = 0; mt < 2; mt++)
#pragma unroll
        for (int nt = 0; nt < 4; nt++) {
            float2 bv = *reinterpret_cast<const float2*>(&b[wn * 32 + nt * 8 + tig * 2]);
            acc[mt][nt][0] = bv.x; acc[mt][nt][1] = bv.y;
            acc[mt][nt][2] = bv.x; acc[mt][nt][3] = bv.y;
        }
    mma_tiles_hi<3, 4, 36>(sA, sW, acc, wm, wn * 32, gid, tig);
#pragma unroll
    for (int mt = 0; mt < 2; mt++)
#pragma unroll
        for (int nt = 0; nt < 4; nt++) {
            int row = wm * 32 + mt * 16 + gid;
            int cw = wn * 16 + nt * 4 + tig;
            int e = e0 + row;
            if (e < EE)     g_ea[(size_t)e * 32 + cw]       = pack2(acc[mt][nt][0], acc[mt][nt][1]);
            if (e + 8 < EE) g_ea[(size_t)(e + 8) * 32 + cw] = pack2(acc[mt][nt][2], acc[mt][nt][3]);
        }
}

// ------------------------------------------------------------------ fused precompute (+ BN/update of previous layer)
__global__ __launch_bounds__(256) void k_precompute(int layer, int do_update) {
    extern __shared__ unsigned dyn[];
    unsigned* sA = dyn;                       // 128*36
    unsigned* sW = dyn + 128 * 36;            // 192*36 hi only
    int tid = threadIdx.x, n0 = blockIdx.x * 128;
    int warp = tid >> 5, lane = tid & 31;
    int wm = warp >> 1, wn = warp & 1;
    int gid = lane >> 2, tig = lane & 3;
    if (blockIdx.x == 0 && tid < 128) g_stats[tid] = 0.0;

    {
        const uint4* src = reinterpret_cast<const uint4*>(g_wpre[layer]);
        uint4* dst = reinterpret_cast<uint4*>(sW);
        for (int idx = tid; idx < 192 * 36 / 4; idx += 256) dst[idx] = src[idx];
    }
    for (int idx = tid; idx < 128 * 32; idx += 256) {
        int nr = idx >> 5, cw = idx & 31;
        int n = n0 + nr;
        if (n < NN) {
            size_t off = (size_t)n * 64 + cw * 2;
            float2 h = *reinterpret_cast<const float2*>(&g_h[off]);
            if (do_update) {
                float2 hn = *reinterpret_cast<const float2*>(&g_hnew[off]);
                int j = cw * 2;
                h.x = sp_f(hn.x * g_ab[j]     + g_ab[64 + j])     + h.x;
                h.y = sp_f(hn.y * g_ab[j + 1] + g_ab[64 + j + 1]) + h.y;
                *reinterpret_cast<float2*>(&g_h[off]) = h;
            }
            sA[nr * 36 + cw] = pack2(h.x, h.y);
            *reinterpret_cast<float2*>(&g_hnew[off]) = make_float2(0.f, 0.f);
        } else sA[nr * 36 + cw] = 0u;
    }
    __syncthreads();

    float acc[2][12][4];
#pragma unroll
    for (int mt = 0; mt < 2; mt++)
#pragma unroll
        for (int nt = 0; nt < 12; nt++) {
            int nc = wn * 96 + nt * 8 + tig * 2;
            float2 bv = *reinterpret_cast<const float2*>(&g_bpre[layer][nc]);
            acc[mt][nt][0] = bv.x; acc[mt][nt][1] = bv.y;
            acc[mt][nt][2] = bv.x; acc[mt][nt][3] = bv.y;
        }
    mma_tiles_hi<4, 12, 36>(sA, sW, acc, wm, wn * 96, gid, tig);
#pragma unroll
    for (int mt = 0; mt < 2; mt++)
#pragma unroll
        for (int nt = 0; nt < 12; nt++) {
            int nc = wn * 96 + nt * 8 + tig * 2;
            unsigned* O = nc < 64 ? g_Arh : (nc < 128 ? g_Ach : g_Brh);
            int cw = (nc & 63) >> 1;
            int row = wm * 32 + mt * 16 + gid;
            int n = n0 + row;
            if (n < NN)     O[(size_t)n * 32 + cw]       = pack2(acc[mt][nt][0], acc[mt][nt][1]);
            if (n + 8 < NN) O[(size_t)(n + 8) * 32 + cw] = pack2(acc[mt][nt][2], acc[mt][nt][3]);
        }
}

// ------------------------------------------------------------------ fused edge pipeline
// hi-only weights, ping-pong activation buffers, 4 syncs/tile, 3 CTA/SM
__global__ __launch_bounds__(256, 3) void k_edge(const int* eidx, int layer,
                                                 const float* b2, const float* b4,
                                                 int store_ea) {
    extern __shared__ unsigned dyn[];
    unsigned* s0 = dyn;                    // 128*36
    unsigned* s1 = dyn + 128 * 36;         // 128*36
    unsigned* sW = dyn + 2 * 128 * 36;     // 4 stages * 2304
    __shared__ float sB2[64], sB4[64];
    __shared__ int sRow[128];              // read only before sync(4) each tile
    __shared__ int sCol[2][128];           // double-buffered (stage-4 reads cross tile boundary)

    int tid = threadIdx.x;
    int warp = tid >> 5, lane = tid & 31;
    int wm = warp >> 1, wn = warp & 1;
    int gid = lane >> 2, tig = lane & 3;

    if (tid < 64) { sB2[tid] = b2[tid]; sB4[tid] = b4[tid]; }
    {
        const uint4* src = reinterpret_cast<const uint4*>(&g_wehi[layer][0][0]);
        uint4* dst = reinterpret_cast<uint4*>(sW);
        for (int idx = tid; idx < 4 * 2304 / 4; idx += 256) dst[idx] = src[idx];
    }
    const unsigned* W1h = sW;
    const unsigned* W2h = sW + 2304;
    const unsigned* W3h = sW + 4608;
    const unsigned* W4h = sW + 6912;

    int pb = 0;
    for (int t = blockIdx.x; t < NT_EDGE; t += gridDim.x, pb ^= 1) {
        int e0 = t * 128;
        // sRow: prior-tile readers (stages 1,3) finished before prior sync(4).
        // sCol[pb]: prior tile used sCol[pb^1]; s0: prior readers (st1,st3) done pre-sync(4).
        if (tid < 128) {
            int e = e0 + tid; if (e >= EE) e = EE - 1;
            sRow[tid] = clampi(eidx[e], NN);
            sCol[pb][tid] = clampi(eidx[EE + e], NN);
        }
        for (int idx = tid; idx < 128 * 32; idx += 256) {
            int er = idx >> 5, cw = idx & 31;
            int e = e0 + er; if (e >= EE) e = EE - 1;
            s0[er * 36 + cw] = g_ea[(size_t)e * 32 + cw];
        }
        __syncthreads();                                        // (1)
        const int* col_ = sCol[pb];

        float acc[2][4][4];

        // ---- stage 1: s1 = sp(s0 @ W1c + Ar[row] + Ac[col])
#pragma unroll
        for (int mt = 0; mt < 2; mt++)
#pragma unroll
            for (int nt = 0; nt < 4; nt++) {
                int row = wm * 32 + mt * 16 + gid;
                int cw = wn * 16 + nt * 4 + tig;
                float2 a0 = up2(g_Arh[(size_t)sRow[row] * 32 + cw]);
                float2 q0 = up2(g_Ach[(size_t)col_[row] * 32 + cw]);
                float2 a1 = up2(g_Arh[(size_t)sRow[row + 8] * 32 + cw]);
                float2 q1 = up2(g_Ach[(size_t)col_[row + 8] * 32 + cw]);
                acc[mt][nt][0] = a0.x + q0.x; acc[mt][nt][1] = a0.y + q0.y;
                acc[mt][nt][2] = a1.x + q1.x; acc[mt][nt][3] = a1.y + q1.y;
            }
        mma_tiles_hi<4, 4, 36>(s0, W1h, acc, wm, wn * 32, gid, tig);
#pragma unroll
        for (int mt = 0; mt < 2; mt++)
#pragma unroll
            for (int nt = 0; nt < 4; nt++) {
                int row = wm * 32 + mt * 16 + gid;
                int cw = wn * 16 + nt * 4 + tig;
                s1[row * 36 + cw]       = pack2(sp_f(acc[mt][nt][0]), sp_f(acc[mt][nt][1]));
                s1[(row + 8) * 36 + cw] = pack2(sp_f(acc[mt][nt][2]), sp_f(acc[mt][nt][3]));
            }
        __syncthreads();                                        // (2)

        // ---- stage 2: s0 = s1 @ W2 + b2 (+gmem)
#pragma unroll
        for (int mt = 0; mt < 2; mt++)
#pragma unroll
            for (int nt = 0; nt < 4; nt++) {
                int col = wn * 32 + nt * 8 + tig * 2;
                float2 bv = *reinterpret_cast<const float2*>(&sB2[col]);
                acc[mt][nt][0] = bv.x; acc[mt][nt][1] = bv.y;
                acc[mt][nt][2] = bv.x; acc[mt][nt][3] = bv.y;
            }
        mma_tiles_hi<4, 4, 36>(s1, W2h, acc, wm, wn * 32, gid, tig);
#pragma unroll
        for (int mt = 0; mt < 2; mt++)
#pragma unroll
            for (int nt = 0; nt < 4; nt++) {
                int row = wm * 32 + mt * 16 + gid;
                int cw = wn * 16 + nt * 4 + tig;
                unsigned p0 = pack2(acc[mt][nt][0], acc[mt][nt][1]);
                unsigned p1 = pack2(acc[mt][nt][2], acc[mt][nt][3]);
                s0[row * 36 + cw]       = p0;
                s0[(row + 8) * 36 + cw] = p1;
                if (store_ea) {
                    int e = e0 + row;
                    if (e < EE)     g_ea[(size_t)e * 32 + cw]       = p0;
                    if (e + 8 < EE) g_ea[(size_t)(e + 8) * 32 + cw] = p1;
                }
            }
        __syncthreads();                                        // (3)

        // ---- stage 3: s1 = sp(s0 @ W3 + Br[row])
#pragma unroll
        for (int mt = 0; mt < 2; mt++)
#pragma unroll
            for (int nt = 0; nt < 4; nt++) {
                int row = wm * 32 + mt * 16 + gid;
                int cw = wn * 16 + nt * 4 + tig;
                float2 v0 = up2(g_Brh[(size_t)sRow[row] * 32 + cw]);
                float2 v1 = up2(g_Brh[(size_t)sRow[row + 8] * 32 + cw]);
                acc[mt][nt][0] = v0.x; acc[mt][nt][1] = v0.y;
                acc[mt][nt][2] = v1.x; acc[mt][nt][3] = v1.y;
            }
        mma_tiles_hi<4, 4, 36>(s0, W3h, acc, wm, wn * 32, gid, tig);
#pragma unroll
        for (int mt = 0; mt < 2; mt++)
#pragma unroll
            for (int nt = 0; nt < 4; nt++) {
                int row = wm * 32 + mt * 16 + gid;
                int cw = wn * 16 + nt * 4 + tig;
                s1[row * 36 + cw]       = pack2(sp_f(acc[mt][nt][0]), sp_f(acc[mt][nt][1]));
                s1[(row + 8) * 36 + cw] = pack2(sp_f(acc[mt][nt][2]), sp_f(acc[mt][nt][3]));
            }
        __syncthreads();                                        // (4)

        // ---- stage 4: msg = s1 @ W4 + b4 -> scatter (no trailing sync)
#pragma unroll
        for (int mt = 0; mt < 2; mt++)
#pragma unroll
            for (int nt = 0; nt < 4; nt++) {
                int col = wn * 32 + nt * 8 + tig * 2;
                float2 bv = *reinterpret_cast<const float2*>(&sB4[col]);
                acc[mt][nt][0] = bv.x; acc[mt][nt][1] = bv.y;
                acc[mt][nt][2] = bv.x; acc[mt][nt][3] = bv.y;
            }
        mma_tiles_hi<4, 4, 36>(s1, W4h, acc, wm, wn * 32, gid, tig);
#pragma unroll
        for (int mt = 0; mt < 2; mt++)
#pragma unroll
            for (int nt = 0; nt < 4; nt++) {
                int row = wm * 32 + mt * 16 + gid;
                int col = wn * 32 + nt * 8 + tig * 2;
                int e = e0 + row;
                if (e < EE)
                    red2(&g_hnew[(size_t)col_[row] * 64 + col], acc[mt][nt][0], acc[mt][nt][1]);
                if (e + 8 < EE)
                    red2(&g_hnew[(size_t)col_[row + 8] * 64 + col], acc[mt][nt][2], acc[mt][nt][3]);
            }
    }
}

// ------------------------------------------------------------------ tail kernels
__global__ void k_stats() {
    int c = threadIdx.x & 63, rr = threadIdx.x >> 6;
    double s = 0.0, s2 = 0.0;
    for (int n = blockIdx.x * 4 + rr; n < NN; n += gridDim.x * 4) {
        float v = g_hnew[n * 64 + c];
        s += v; s2 += (double)v * v;
    }
    __shared__ double sh[8][64];
    sh[rr][c] = s; sh[4 + rr][c] = s2;
    __syncthreads();
    if (rr == 0) {
        atomicAdd(&g_stats[c],      sh[0][c] + sh[1][c] + sh[2][c] + sh[3][c]);
        atomicAdd(&g_stats[64 + c], sh[4][c] + sh[5][c] + sh[6][c] + sh[7][c]);
    }
}

__global__ void k_finalize(const float* gamma, const float* beta) {
    int j = threadIdx.x;
    double mu = g_stats[j] / (double)NN;
    double var = g_stats[64 + j] / (double)NN - mu * mu;
    float a = rsqrtf((float)var + 1e-5f) * gamma[j];
    g_ab[j] = a;
    g_ab[64 + j] = beta[j] - (float)mu * a;
}

__global__ void k_update_pool(const int* batch) {
    int idx = blockIdx.x * 256 + threadIdx.x;
    int j = idx & 63;
    float v = g_hnew[idx] * g_ab[j] + g_ab[64 + j];
    float h = sp_f(v) + g_h[idx];
    int b = clampi(batch[idx >> 6], GG);
    atomicAdd(&g_pool[b * 64 + j], h);
    if (j == 0) atomicAdd(&g_cnt[b], 1.f);
}

__global__ void k_predict(const float* W1, const float* b1,
                          const float* W2, const float* b2,
                          const float* W3, const float* b3, float* out) {
    __shared__ float gr[64], z1[128], z2[128];
    __shared__ float red[4];
    int g = blockIdx.x, t = threadIdx.x;
    if (t < 64) gr[t] = g_pool[g * 64 + t] / fmaxf(g_cnt[g], 1.f);
    __syncthreads();
    float acc = b1[t];
    for (int k = 0; k < 64; k++) acc = fmaf(gr[k], W1[k * 128 + t], acc);
    z1[t] = sp_f(acc);
    __syncthreads();
    acc = b2[t];
    for (int k = 0; k < 128; k++) acc = fmaf(z1[k], W2[k * 128 + t], acc);
    z2[t] = sp_f(acc);
    __syncthreads();
    float v = z2[t] * W3[t];
    for (int o = 16; o > 0; o >>= 1) v += __shfl_down_sync(0xffffffff, v, o);
    if ((t & 31) == 0) red[t >> 5] = v;
    __syncthreads();
    if (t == 0) out[g] = red[0] + red[1] + red[2] + red[3] + b3[0];
}

// ------------------------------------------------------------------ launch
extern "C" void kernel_launch(void* const* d_in, const int* in_sizes, int n_in,
                              void* d_out, int out_size) {
    const float* x         = (const float*)d_in[0];
    const float* edge_attr = (const float*)d_in[1];
    const float* charge    = (const float*)d_in[2];
    const int*   eidx      = (const int*)d_in[3];
    const int*   batch     = (const int*)d_in[4];
    const float* W_charge  = (const float*)d_in[5];
    const float* b_charge  = (const float*)d_in[6];
    const float* W_atom    = (const float*)d_in[7];
    const float* b_atom    = (const float*)d_in[8];
    const float* W_bond    = (const float*)d_in[9];
    const float* b_bond    = (const float*)d_in[10];
    const float* nu_W1     = (const float*)d_in[11];
    const float* nu_b1     = (const float*)d_in[12];
    const float* nu_W2     = (const float*)d_in[13];
    const float* nu_b2     = (const float*)d_in[14];
    const float* eu_W1     = (const float*)d_in[15];
    const float* eu_b1     = (const float*)d_in[16];
    const float* eu_W2     = (const float*)d_in[17];
    const float* eu_b2     = (const float*)d_in[18];
    const float* bn_g      = (const float*)d_in[19];
    const float* bn_b      = (const float*)d_in[20];
    const float* p_W1      = (const float*)d_in[21];
    const float* p_b1      = (const float*)d_in[22];
    const float* p_W2      = (const float*)d_in[23];
    const float* p_b2      = (const float*)d_in[24];
    const float* p_W3      = (const float*)d_in[25];
    const float* p_b3      = (const float*)d_in[26];
    float* out = (float*)d_out;

    const int PRE_SMEM  = (128 * 36 + 192 * 36) * 4;           // 46080
    const int EDGE_SMEM = (2 * 128 * 36 + 4 * 2304) * 4;       // 73728
    const int EN_SMEM   = (128 * 68 + 2 * 64 * 68) * 4;        // 69632
    const int EB_SMEM   = (5248 + 128 * 36 + 64 * 36) * 4;     // 48640
    cudaFuncSetAttribute(k_precompute, cudaFuncAttributeMaxDynamicSharedMemorySize, PRE_SMEM);
    cudaFuncSetAttribute(k_edge, cudaFuncAttributeMaxDynamicSharedMemorySize, EDGE_SMEM);
    cudaFuncSetAttribute(k_embed_nodes_mma, cudaFuncAttributeMaxDynamicSharedMemorySize, EN_SMEM);
    cudaFuncSetAttribute(k_embed_edges_mma, cudaFuncAttributeMaxDynamicSharedMemorySize, EB_SMEM);

    k_charge<<<64, 256>>>(charge, W_charge, b_charge);
    k_cvt_all<<<23, 256>>>(eu_W1, eu_b1, nu_W1, nu_b1, eu_W2, nu_W2, W_bond, W_atom);
    k_embed_nodes_mma<<<(NN + 127) / 128, 256, EN_SMEM>>>(x, batch, b_atom);
    k_embed_edges_mma<<<NT_EDGE, 256, EB_SMEM>>>(edge_attr, b_bond);

    for (int i = 0; i < LL; i++) {
        k_precompute<<<(NN + 127) / 128, 256, PRE_SMEM>>>(i, i > 0 ? 1 : 0);
        k_edge<<<444, 256, EDGE_SMEM>>>(eidx, i, eu_b2 + i * 64, nu_b2 + i * 64,
                                        i < LL - 1 ? 1 : 0);
        k_stats<<<256, 256>>>();
        k_finalize<<<1, 64>>>(bn_g + i * 64, bn_b + i * 64);
    }
    k_update_pool<<<(NN * DD) / 256, 256>>>(batch);
    k_predict<<<GG, 128>>>(p_W1, p_b1, p_W2, p_b2, p_W3, p_b3, out);
}

// round 15
// speedup vs baseline: 1.0140x; 1.0140x over previous
#include <cuda_runtime.h>
#include <cuda_bf16.h>
#include <math.h>

#define NN 50000
#define EE 500000
#define GG 256
#define DD 64
#define LL 3
#define NT_EDGE ((EE + 127) / 128)
#define STATS_BLOCKS 256

// ------------------------------------------------------------------ globals
__device__ float    g_h[NN * DD];
__device__ unsigned g_ea[(size_t)EE * 32];      // bf16x2 words
__device__ unsigned g_Arh[NN * 32];             // bf16x2 gather tables
__device__ unsigned g_Ach[NN * 32];
__device__ unsigned g_Brh[NN * 32];
__device__ float    g_hnew[NN * DD];
__device__ double   g_stats[2 * DD];
__device__ unsigned g_stats_ctr;
__device__ float    g_ab[2 * DD];
__device__ float    g_pool[GG * DD];
__device__ float    g_cnt[GG];
__device__ float    g_cf[GG * 16];

__device__ unsigned g_wbond[64 * 36];           // hi-only
__device__ unsigned g_wpre[LL][192 * 36];       // hi-only
__device__ unsigned g_wehi[LL][4][64 * 36];     // hi-only
__device__ unsigned g_watom[2][64 * 68];        // hi+lo (fp32 output path)
__device__ float    g_bpre[LL][192];

__device__ __forceinline__ float sp_f(float x) {
    return x > 15.f ? x : __logf(1.f + __expf(x));
}
__device__ __forceinline__ int clampi(int v, int hi) {
    return v < 0 ? 0 : (v >= hi ? hi - 1 : v);
}
__device__ __forceinline__ unsigned pack2(float x, float y) {
    __nv_bfloat162 h = __floats2bfloat162_rn(x, y);
    return *reinterpret_cast<unsigned*>(&h);
}
__device__ __forceinline__ float2 up2(unsigned u) {
    __nv_bfloat162 h = *reinterpret_cast<__nv_bfloat162*>(&u);
    return __bfloat1622float2(h);
}
__device__ __forceinline__ void red2(float* a, float x, float y) {
    asm volatile("red.global.add.v2.f32 [%0], {%1,%2};" :: "l"(a), "f"(x), "f"(y) : "memory");
}
__device__ __forceinline__ void mma_bf16(float& c0, float& c1, float& c2, float& c3,
                                         unsigned a0, unsigned a1, unsigned a2, unsigned a3,
                                         unsigned b0, unsigned b1) {
    asm volatile("mma.sync.aligned.m16n8k16.row.col.f32.bf16.bf16.f32 "
                 "{%0,%1,%2,%3}, {%4,%5,%6,%7}, {%8,%9}, {%0,%1,%2,%3};\n"
                 : "+f"(c0), "+f"(c1), "+f"(c2), "+f"(c3)
                 : "r"(a0), "r"(a1), "r"(a2), "r"(a3), "r"(b0), "r"(b1));
}

// hi+lo split-weight version (embed_nodes only)
template<int K0, int NT, int LD>
__device__ __forceinline__ void mma_tiles(const unsigned* sA, const unsigned* sWhi,
                                          const unsigned* sWlo, float acc[][NT][4],
                                          int wm, int wcol0, int gid, int tig) {
#pragma unroll
    for (int k0 = 0; k0 < K0; k0++) {
        unsigned a[2][4];
#pragma unroll
        for (int mt = 0; mt < 2; mt++) {
            const unsigned* base = &sA[(wm * 32 + mt * 16 + gid) * LD + k0 * 8 + tig];
            a[mt][0] = base[0];
            a[mt][1] = base[8 * LD];
            a[mt][2] = base[4];
            a[mt][3] = base[8 * LD + 4];
        }
#pragma unroll
        for (int nt = 0; nt < NT; nt++) {
            int off = (wcol0 + nt * 8 + gid) * LD + k0 * 8 + tig;
            unsigned bh0 = sWhi[off], bh1 = sWhi[off + 4];
            unsigned bl0 = sWlo[off], bl1 = sWlo[off + 4];
#pragma unroll
            for (int mt = 0; mt < 2; mt++) {
                mma_bf16(acc[mt][nt][0], acc[mt][nt][1], acc[mt][nt][2], acc[mt][nt][3],
                         a[mt][0], a[mt][1], a[mt][2], a[mt][3], bh0, bh1);
                mma_bf16(acc[mt][nt][0], acc[mt][nt][1], acc[mt][nt][2], acc[mt][nt][3],
                         a[mt][0], a[mt][1], a[mt][2], a[mt][3], bl0, bl1);
            }
        }
    }
}

// hi-only version
template<int K0, int NT, int LD>
__device__ __forceinline__ void mma_tiles_hi(const unsigned* sA, const unsigned* sWhi,
                                             float acc[][NT][4],
                                             int wm, int wcol0, int gid, int tig) {
#pragma unroll
    for (int k0 = 0; k0 < K0; k0++) {
        unsigned a[2][4];
#pragma unroll
        for (int mt = 0; mt < 2; mt++) {
            const unsigned* base = &sA[(wm * 32 + mt * 16 + gid) * LD + k0 * 8 + tig];
            a[mt][0] = base[0];
            a[mt][1] = base[8 * LD];
            a[mt][2] = base[4];
            a[mt][3] = base[8 * LD + 4];
        }
#pragma unroll
        for (int nt = 0; nt < NT; nt++) {
            int off = (wcol0 + nt * 8 + gid) * LD + k0 * 8 + tig;
            unsigned bh0 = sWhi[off], bh1 = sWhi[off + 4];
#pragma unroll
            for (int mt = 0; mt < 2; mt++)
                mma_bf16(acc[mt][nt][0], acc[mt][nt][1], acc[mt][nt][2], acc[mt][nt][3],
                         a[mt][0], a[mt][1], a[mt][2], a[mt][3], bh0, bh1);
        }
    }
}

// ------------------------------------------------------------------ one-time weight conversion
__global__ void k_cvt_all(const float* eu_W1, const float* eu_b1,
                          const float* nu_W1, const float* nu_b1,
                          const float* eu_W2, const float* nu_W2,
                          const float* W_bond, const float* W_atom) {
    int b = blockIdx.x, tid = threadIdx.x;
    if (b == 22) {   // W_atom: hi+lo
        __nv_bfloat16* hhi = reinterpret_cast<__nv_bfloat16*>(g_watom[0]);
        __nv_bfloat16* hlo = reinterpret_cast<__nv_bfloat16*>(g_watom[1]);
        for (int idx = tid; idx < 112 * 64; idx += 256) {
            int k = idx >> 6, n = idx & 63;
            float w = (k < 108) ? W_atom[k * 64 + n] : 0.f;
            __nv_bfloat16 hi = __float2bfloat16(w);
            float lo = w - __bfloat162float(hi);
            hhi[(size_t)n * 136 + k] = hi;
            hlo[(size_t)n * 136 + k] = __float2bfloat16(lo);
        }
        return;
    }
    const float* src; int i = 0, ncoff = 0, validK = 64;
    unsigned* dhi = 0;
    if (b == 0) {
        src = W_bond; validK = 41;
        dhi = g_wbond;
        for (int idx = tid; idx < LL * 192; idx += 256) {
            int ii = idx / 192, n = idx % 192;
            float v = 0.f;
            if (n < 64)        v = eu_b1[ii * 64 + n];
            else if (n >= 128) v = nu_b1[ii * 64 + (n - 128)];
            g_bpre[ii][n] = v;
        }
        if (tid == 0) g_stats_ctr = 0;
    } else {
        i = (b - 1) / 7; int j = (b - 1) % 7;
        const float* euW1 = eu_W1 + (size_t)i * 12288;
        const float* nuW1 = nu_W1 + (size_t)i * 8192;
        switch (j) {
            case 0: src = euW1;            dhi = g_wpre[i]; ncoff = 0;   break;
            case 1: src = euW1 + 4096;     dhi = g_wpre[i]; ncoff = 64;  break;
            case 2: src = nuW1;            dhi = g_wpre[i]; ncoff = 128; break;
            case 3: src = euW1 + 8192;     dhi = g_wehi[i][0]; break;
            case 4: src = eu_W2 + (size_t)i * 4096; dhi = g_wehi[i][1]; break;
            case 5: src = nuW1 + 4096;     dhi = g_wehi[i][2]; break;
            default: src = nu_W2 + (size_t)i * 4096; dhi = g_wehi[i][3]; break;
        }
    }
    __nv_bfloat16* hhi = reinterpret_cast<__nv_bfloat16*>(dhi);
    for (int idx = tid; idx < 4096; idx += 256) {
        int k = idx >> 6, n = idx & 63;
        float w = (k < validK) ? src[k * 64 + n] : 0.f;
        hhi[(size_t)(n + ncoff) * 72 + k] = __float2bfloat16(w);
    }
}

// ------------------------------------------------------------------ small kernels
__global__ void k_charge(const float* charge, const float* Wc, const float* bc) {
    int i = blockIdx.x * 256 + threadIdx.x;
    if (i < GG * 16) g_cf[i] = charge[i >> 4] * Wc[i & 15] + bc[i & 15];
    if (i < GG * DD) g_pool[i] = 0.f;
    if (i < GG) g_cnt[i] = 0.f;
}

// ------------------------------------------------------------------ node embedding via MMA (K=112)
__global__ __launch_bounds__(256) void k_embed_nodes_mma(
    const float* x, const int* batch, const float* b) {
    extern __shared__ unsigned dyn[];
    unsigned* sA = dyn;
    unsigned* sW = dyn + 128 * 68;
    int tid = threadIdx.x, n0 = blockIdx.x * 128;
    int warp = tid >> 5, lane = tid & 31;
    int wm = warp >> 1, wn = warp & 1;
    int gid = lane >> 2, tig = lane & 3;

    {
        const uint4* src = reinterpret_cast<const uint4*>(g_watom[0]);
        uint4* dst = reinterpret_cast<uint4*>(sW);
        for (int idx = tid; idx < 2 * 64 * 68 / 4; idx += 256) dst[idx] = src[idx];
    }
    for (int idx = tid; idx < 128 * 56; idx += 256) {
        int nr = idx / 56, kw = idx - nr * 56;
        int n = n0 + nr; if (n >= NN) n = NN - 1;
        int k = kw * 2;
        float v0, v1;
        int bb = clampi(batch[n], GG);
        v0 = (k < 92)      ? x[(size_t)n * 92 + k]
           : (k < 108)     ? g_cf[bb * 16 + (k - 92)] : 0.f;
        int k1 = k + 1;
        v1 = (k1 < 92)     ? x[(size_t)n * 92 + k1]
           : (k1 < 108)    ? g_cf[bb * 16 + (k1 - 92)] : 0.f;
        sA[nr * 68 + kw] = pack2(v0, v1);
    }
    __syncthreads();

    float acc[2][4][4];
#pragma unroll
    for (int mt = 0; mt < 2; mt++)
#pragma unroll
        for (int nt = 0; nt < 4; nt++) {
            float2 bv = *reinterpret_cast<const float2*>(&b[wn * 32 + nt * 8 + tig * 2]);
            acc[mt][nt][0] = bv.x; acc[mt][nt][1] = bv.y;
            acc[mt][nt][2] = bv.x; acc[mt][nt][3] = bv.y;
        }
    mma_tiles<7, 4, 68>(sA, sW, sW + 64 * 68, acc, wm, wn * 32, gid, tig);
#pragma unroll
    for (int mt = 0; mt < 2; mt++)
#pragma unroll
        for (int nt = 0; nt < 4; nt++) {
            int row = wm * 32 + mt * 16 + gid;
            int col = wn * 32 + nt * 8 + tig * 2;
            int n = n0 + row;
            if (n < NN)
                *reinterpret_cast<float2*>(&g_h[(size_t)n * 64 + col]) =
                    make_float2(acc[mt][nt][0], acc[mt][nt][1]);
            if (n + 8 < NN)
                *reinterpret_cast<float2*>(&g_h[(size_t)(n + 8) * 64 + col]) =
                    make_float2(acc[mt][nt][2], acc[mt][nt][3]);
        }
}

// ------------------------------------------------------------------ edge embedding (hi-only)
__global__ __launch_bounds__(256) void k_embed_edges_mma(const float* ea, const float* b) {
    extern __shared__ float dynf[];
    float*    flat = dynf;                               // 128*41
    unsigned* sA   = reinterpret_cast<unsigned*>(dynf + 5248);
    unsigned* sW   = sA + 128 * 36;                      // 64*36 hi only
    int tid = threadIdx.x, e0 = blockIdx.x * 128;
    int warp = tid >> 5, lane = tid & 31;
    int wm = warp >> 1, wn = warp & 1;
    int gid = lane >> 2, tig = lane & 3;

    {
        const uint4* src = reinterpret_cast<const uint4*>(g_wbond);
        uint4* dst = reinterpret_cast<uint4*>(sW);
        for (int idx = tid; idx < 64 * 36 / 4; idx += 256) dst[idx] = src[idx];
    }
    int valid = EE - e0; if (valid > 128) valid = 128;
    int nload = valid * 41;
    for (int idx = tid; idx < nload; idx += 256)
        flat[idx] = __ldcg(&ea[(size_t)e0 * 41 + idx]);
    __syncthreads();
    for (int idx = tid; idx < 128 * 24; idx += 256) {
        int er = idx / 24, kw = idx - er * 24;
        int k = kw * 2;
        float v0 = 0.f, v1 = 0.f;
        if (er < valid) {
            if (k < 41)     v0 = flat[er * 41 + k];
            if (k + 1 < 41) v1 = flat[er * 41 + k + 1];
        }
        sA[er * 36 + kw] = pack2(v0, v1);
    }
    __syncthreads();

    float acc[2][4][4];
#pragma unroll
    for (int mt = 0; mt < 2; mt++)
#pragma unroll
        for (int nt = 0; nt < 4; nt++) {
            float2 bv = *reinterpret_cast<const float2*>(&b[wn * 32 + nt * 8 + tig * 2]);
            acc[mt][nt][0] = bv.x; acc[mt][nt][1] = bv.y;
            acc[mt][nt][2] = bv.x; acc[mt][nt][3] = bv.y;
        }
    mma_tiles_hi<3, 4, 36>(sA, sW, acc, wm, wn * 32, gid, tig);
#pragma unroll
    for (int mt = 0; mt < 2; mt++)
#pragma unroll
        for (int nt = 0; nt < 4; nt++) {
            int row = wm * 32 + mt * 16 + gid;
            int cw = wn * 16 + nt * 4 + tig;
            int e = e0 + row;
            if (e < EE)     __stcg(&g_ea[(size_t)e * 32 + cw],       pack2(acc[mt][nt][0], acc[mt][nt][1]));
            if (e + 8 < EE) __stcg(&g_ea[(size_t)(e + 8) * 32 + cw], pack2(acc[mt][nt][2], acc[mt][nt][3]));
        }
}

// ------------------------------------------------------------------ fused precompute (+ BN/update of previous layer)
__global__ __launch_bounds__(256) void k_precompute(int layer, int do_update) {
    extern __shared__ unsigned dyn[];
    unsigned* sA = dyn;                       // 128*36
    unsigned* sW = dyn + 128 * 36;            // 192*36 hi only
    int tid = threadIdx.x, n0 = blockIdx.x * 128;
    int warp = tid >> 5, lane = tid & 31;
    int wm = warp >> 1, wn = warp & 1;
    int gid = lane >> 2, tig = lane & 3;

    {
        const uint4* src = reinterpret_cast<const uint4*>(g_wpre[layer]);
        uint4* dst = reinterpret_cast<uint4*>(sW);
        for (int idx = tid; idx < 192 * 36 / 4; idx += 256) dst[idx] = src[idx];
    }
    for (int idx = tid; idx < 128 * 32; idx += 256) {
        int nr = idx >> 5, cw = idx & 31;
        int n = n0 + nr;
        if (n < NN) {
            size_t off = (size_t)n * 64 + cw * 2;
            float2 h = *reinterpret_cast<const float2*>(&g_h[off]);
            if (do_update) {
                float2 hn = *reinterpret_cast<const float2*>(&g_hnew[off]);
                int j = cw * 2;
                h.x = sp_f(hn.x * g_ab[j]     + g_ab[64 + j])     + h.x;
                h.y = sp_f(hn.y * g_ab[j + 1] + g_ab[64 + j + 1]) + h.y;
                *reinterpret_cast<float2*>(&g_h[off]) = h;
            }
            sA[nr * 36 + cw] = pack2(h.x, h.y);
            *reinterpret_cast<float2*>(&g_hnew[off]) = make_float2(0.f, 0.f);
        } else sA[nr * 36 + cw] = 0u;
    }
    __syncthreads();

    float acc[2][12][4];
#pragma unroll
    for (int mt = 0; mt < 2; mt++)
#pragma unroll
        for (int nt = 0; nt < 12; nt++) {
            int nc = wn * 96 + nt * 8 + tig * 2;
            float2 bv = *reinterpret_cast<const float2*>(&g_bpre[layer][nc]);
            acc[mt][nt][0] = bv.x; acc[mt][nt][1] = bv.y;
            acc[mt][nt][2] = bv.x; acc[mt][nt][3] = bv.y;
        }
    mma_tiles_hi<4, 12, 36>(sA, sW, acc, wm, wn * 96, gid, tig);
#pragma unroll
    for (int mt = 0; mt < 2; mt++)
#pragma unroll
        for (int nt = 0; nt < 12; nt++) {
            int nc = wn * 96 + nt * 8 + tig * 2;
            unsigned* O = nc < 64 ? g_Arh : (nc < 128 ? g_Ach : g_Brh);
            int cw = (nc & 63) >> 1;
            int row = wm * 32 + mt * 16 + gid;
            int n = n0 + row;
            if (n < NN)     O[(size_t)n * 32 + cw]       = pack2(acc[mt][nt][0], acc[mt][nt][1]);
            if (n + 8 < NN) O[(size_t)(n + 8) * 32 + cw] = pack2(acc[mt][nt][2], acc[mt][nt][3]);
        }
}

// ------------------------------------------------------------------ fused edge pipeline (R13 config + cg streaming)
__global__ __launch_bounds__(256, 3) void k_edge(const int* eidx, int layer,
                                                 const float* b2, const float* b4,
                                                 int store_ea) {
    extern __shared__ unsigned dyn[];
    unsigned* sA = dyn;                    // 128*36
    unsigned* sW = dyn + 128 * 36;         // 4 stages * 2304
    __shared__ float sB2[64], sB4[64];
    __shared__ int sRow[128], sCol[128];

    int tid = threadIdx.x;
    int warp = tid >> 5, lane = tid & 31;
    int wm = warp >> 1, wn = warp & 1;
    int gid = lane >> 2, tig = lane & 3;

    if (tid < 64) { sB2[tid] = b2[tid]; sB4[tid] = b4[tid]; }
    {
        const uint4* src = reinterpret_cast<const uint4*>(&g_wehi[layer][0][0]);
        uint4* dst = reinterpret_cast<uint4*>(sW);
        for (int idx = tid; idx < 4 * 2304 / 4; idx += 256) dst[idx] = src[idx];
    }
    const unsigned* W1h = sW;
    const unsigned* W2h = sW + 2304;
    const unsigned* W3h = sW + 4608;
    const unsigned* W4h = sW + 6912;

    for (int t = blockIdx.x; t < NT_EDGE; t += gridDim.x) {
        int e0 = t * 128;
        __syncthreads();
        if (tid < 128) {
            int e = e0 + tid; if (e >= EE) e = EE - 1;
            sRow[tid] = clampi(__ldcg(&eidx[e]), NN);
            sCol[tid] = clampi(__ldcg(&eidx[EE + e]), NN);
        }
        for (int idx = tid; idx < 128 * 32; idx += 256) {
            int er = idx >> 5, cw = idx & 31;
            int e = e0 + er; if (e >= EE) e = EE - 1;
            sA[er * 36 + cw] = __ldcg(&g_ea[(size_t)e * 32 + cw]);
        }
        __syncthreads();

        float acc[2][4][4];

        // ---- stage 1
#pragma unroll
        for (int mt = 0; mt < 2; mt++)
#pragma unroll
            for (int nt = 0; nt < 4; nt++) {
                int row = wm * 32 + mt * 16 + gid;
                int cw = wn * 16 + nt * 4 + tig;
                float2 a0 = up2(g_Arh[(size_t)sRow[row] * 32 + cw]);
                float2 q0 = up2(g_Ach[(size_t)sCol[row] * 32 + cw]);
                float2 a1 = up2(g_Arh[(size_t)sRow[row + 8] * 32 + cw]);
                float2 q1 = up2(g_Ach[(size_t)sCol[row + 8] * 32 + cw]);
                acc[mt][nt][0] = a0.x + q0.x; acc[mt][nt][1] = a0.y + q0.y;
                acc[mt][nt][2] = a1.x + q1.x; acc[mt][nt][3] = a1.y + q1.y;
            }
        mma_tiles_hi<4, 4, 36>(sA, W1h, acc, wm, wn * 32, gid, tig);
        __syncthreads();
#pragma unroll
        for (int mt = 0; mt < 2; mt++)
#pragma unroll
            for (int nt = 0; nt < 4; nt++) {
                int row = wm * 32 + mt * 16 + gid;
                int cw = wn * 16 + nt * 4 + tig;
                sA[row * 36 + cw]       = pack2(sp_f(acc[mt][nt][0]), sp_f(acc[mt][nt][1]));
                sA[(row + 8) * 36 + cw] = pack2(sp_f(acc[mt][nt][2]), sp_f(acc[mt][nt][3]));
            }
        __syncthreads();

        // ---- stage 2
#pragma unroll
        for (int mt = 0; mt < 2; mt++)
#pragma unroll
            for (int nt = 0; nt < 4; nt++) {
                int col = wn * 32 + nt * 8 + tig * 2;
                float2 bv = *reinterpret_cast<const float2*>(&sB2[col]);
                acc[mt][nt][0] = bv.x; acc[mt][nt][1] = bv.y;
                acc[mt][nt][2] = bv.x; acc[mt][nt][3] = bv.y;
            }
        mma_tiles_hi<4, 4, 36>(sA, W2h, acc, wm, wn * 32, gid, tig);
        __syncthreads();
#pragma unroll
        for (int mt = 0; mt < 2; mt++)
#pragma unroll
            for (int nt = 0; nt < 4; nt++) {
                int row = wm * 32 + mt * 16 + gid;
                int cw = wn * 16 + nt * 4 + tig;
                unsigned p0 = pack2(acc[mt][nt][0], acc[mt][nt][1]);
                unsigned p1 = pack2(acc[mt][nt][2], acc[mt][nt][3]);
                sA[row * 36 + cw]       = p0;
                sA[(row + 8) * 36 + cw] = p1;
                if (store_ea) {
                    int e = e0 + row;
                    if (e < EE)     __stcg(&g_ea[(size_t)e * 32 + cw],       p0);
                    if (e + 8 < EE) __stcg(&g_ea[(size_t)(e + 8) * 32 + cw], p1);
                }
            }
        __syncthreads();

        // ---- stage 3
#pragma unroll
        for (int mt = 0; mt < 2; mt++)
#pragma unroll
            for (int nt = 0; nt < 4; nt++) {
                int row = wm * 32 + mt * 16 + gid;
                int cw = wn * 16 + nt * 4 + tig;
                float2 v0 = up2(g_Brh[(size_t)sRow[row] * 32 + cw]);
                float2 v1 = up2(g_Brh[(size_t)sRow[row + 8] * 32 + cw]);
                acc[mt][nt][0] = v0.x; acc[mt][nt][1] = v0.y;
                acc[mt][nt][2] = v1.x; acc[mt][nt][3] = v1.y;
            }
        mma_tiles_hi<4, 4, 36>(sA, W3h, acc, wm, wn * 32, gid, tig);
        __syncthreads();
#pragma unroll
        for (int mt = 0; mt < 2; mt++)
#pragma unroll
            for (int nt = 0; nt < 4; nt++) {
                int row = wm * 32 + mt * 16 + gid;
                int cw = wn * 16 + nt * 4 + tig;
                sA[row * 36 + cw]       = pack2(sp_f(acc[mt][nt][0]), sp_f(acc[mt][nt][1]));
                sA[(row + 8) * 36 + cw] = pack2(sp_f(acc[mt][nt][2]), sp_f(acc[mt][nt][3]));
            }
        __syncthreads();

        // ---- stage 4 -> scatter
#pragma unroll
        for (int mt = 0; mt < 2; mt++)
#pragma unroll
            for (int nt = 0; nt < 4; nt++) {
                int col = wn * 32 + nt * 8 + tig * 2;
                float2 bv = *reinterpret_cast<const float2*>(&sB4[col]);
                acc[mt][nt][0] = bv.x; acc[mt][nt][1] = bv.y;
                acc[mt][nt][2] = bv.x; acc[mt][nt][3] = bv.y;
            }
        mma_tiles_hi<4, 4, 36>(sA, W4h, acc, wm, wn * 32, gid, tig);
#pragma unroll
        for (int mt = 0; mt < 2; mt++)
#pragma unroll
            for (int nt = 0; nt < 4; nt++) {
                int row = wm * 32 + mt * 16 + gid;
                int col = wn * 32 + nt * 8 + tig * 2;
                int e = e0 + row;
                if (e < EE)
                    red2(&g_hnew[(size_t)sCol[row] * 64 + col], acc[mt][nt][0], acc[mt][nt][1]);
                if (e + 8 < EE)
                    red2(&g_hnew[(size_t)sCol[row + 8] * 64 + col], acc[mt][nt][2], acc[mt][nt][3]);
            }
    }
}

// ------------------------------------------------------------------ stats + fused finalize (last block)
__global__ void k_stats(const float* gamma, const float* beta) {
    int c = threadIdx.x & 63, rr = threadIdx.x >> 6;
    int tid = threadIdx.x;
    double s = 0.0, s2 = 0.0;
    for (int n = blockIdx.x * 4 + rr; n < NN; n += gridDim.x * 4) {
        float v = __ldcg(&g_hnew[n * 64 + c]);
        s += v; s2 += (double)v * v;
    }
    __shared__ double sh[8][64];
    __shared__ int isLast;
    sh[rr][c] = s; sh[4 + rr][c] = s2;
    __syncthreads();
    if (rr == 0) {
        atomicAdd(&g_stats[c],      sh[0][c] + sh[1][c] + sh[2][c] + sh[3][c]);
        atomicAdd(&g_stats[64 + c], sh[4][c] + sh[5][c] + sh[6][c] + sh[7][c]);
    }
    if (tid == 0) {
        __threadfence();
        unsigned done = atomicAdd(&g_stats_ctr, 1u);
        isLast = (done == (unsigned)(gridDim.x - 1));
    }
    __syncthreads();
    if (isLast) {
        if (tid == 0) g_stats_ctr = 0;
        if (tid < 128) g_stats[tid + 128] = 0.0;   // unused guard (no-op range)
        if (tid < 64) {
            double mu = g_stats[tid] / (double)NN;
            double var = g_stats[64 + tid] / (double)NN - mu * mu;
            float a = rsqrtf((float)var + 1e-5f) * gamma[tid];
            g_ab[tid] = a;
            g_ab[64 + tid] = beta[tid] - (float)mu * a;
            g_stats[tid] = 0.0;                    // reset for next layer
            g_stats[64 + tid] = 0.0;
        }
    }
}

__global__ void k_update_pool(const int* batch) {
    int idx = blockIdx.x * 256 + threadIdx.x;
    int j = idx & 63;
    float v = g_hnew[idx] * g_ab[j] + g_ab[64 + j];
    float h = sp_f(v) + g_h[idx];
    int b = clampi(batch[idx >> 6], GG);
    atomicAdd(&g_pool[b * 64 + j], h);
    if (j == 0) atomicAdd(&g_cnt[b], 1.f);
}

__global__ void k_predict(const float* W1, const float* b1,
                          const float* W2, const float* b2,
                          const float* W3, const float* b3, float* out) {
    __shared__ float gr[64], z1[128], z2[128];
    __shared__ float red[4];
    int g = blockIdx.x, t = threadIdx.x;
    if (t < 64) gr[t] = g_pool[g * 64 + t] / fmaxf(g_cnt[g], 1.f);
    __syncthreads();
    float acc = b1[t];
    for (int k = 0; k < 64; k++) acc = fmaf(gr[k], W1[k * 128 + t], acc);
    z1[t] = sp_f(acc);
    __syncthreads();
    acc = b2[t];
    for (int k = 0; k < 128; k++) acc = fmaf(z1[k], W2[k * 128 + t], acc);
    z2[t] = sp_f(acc);
    __syncthreads();
    float v = z2[t] * W3[t];
    for (int o = 16; o > 0; o >>= 1) v += __shfl_down_sync(0xffffffff, v, o);
    if ((t & 31) == 0) red[t >> 5] = v;
    __syncthreads();
    if (t == 0) out[g] = red[0] + red[1] + red[2] + red[3] + b3[0];
}

// ------------------------------------------------------------------ launch
extern "C" void kernel_launch(void* const* d_in, const int* in_sizes, int n_in,
                              void* d_out, int out_size) {
    const float* x         = (const float*)d_in[0];
    const float* edge_attr = (const float*)d_in[1];
    const float* charge    = (const float*)d_in[2];
    const int*   eidx      = (const int*)d_in[3];
    const int*   batch     = (const int*)d_in[4];
    const float* W_charge  = (const float*)d_in[5];
    const float* b_charge  = (const float*)d_in[6];
    const float* W_atom    = (const float*)d_in[7];
    const float* b_atom    = (const float*)d_in[8];
    const float* W_bond    = (const float*)d_in[9];
    const float* b_bond    = (const float*)d_in[10];
    const float* nu_W1     = (const float*)d_in[11];
    const float* nu_b1     = (const float*)d_in[12];
    const float* nu_W2     = (const float*)d_in[13];
    const float* nu_b2     = (const float*)d_in[14];
    const float* eu_W1     = (const float*)d_in[15];
    const float* eu_b1     = (const float*)d_in[16];
    const float* eu_W2     = (const float*)d_in[17];
    const float* eu_b2     = (const float*)d_in[18];
    const float* bn_g      = (const float*)d_in[19];
    const float* bn_b      = (const float*)d_in[20];
    const float* p_W1      = (const float*)d_in[21];
    const float* p_b1      = (const float*)d_in[22];
    const float* p_W2      = (const float*)d_in[23];
    const float* p_b2      = (const float*)d_in[24];
    const float* p_W3      = (const float*)d_in[25];
    const float* p_b3      = (const float*)d_in[26];
    float* out = (float*)d_out;

    const int PRE_SMEM  = (128 * 36 + 192 * 36) * 4;           // 46080
    const int EDGE_SMEM = (128 * 36 + 4 * 2304) * 4;           // 55296
    const int EN_SMEM   = (128 * 68 + 2 * 64 * 68) * 4;        // 69632
    const int EB_SMEM   = (5248 + 128 * 36 + 64 * 36) * 4;     // 48640
    cudaFuncSetAttribute(k_precompute, cudaFuncAttributeMaxDynamicSharedMemorySize, PRE_SMEM);
    cudaFuncSetAttribute(k_edge, cudaFuncAttributeMaxDynamicSharedMemorySize, EDGE_SMEM);
    cudaFuncSetAttribute(k_embed_nodes_mma, cudaFuncAttributeMaxDynamicSharedMemorySize, EN_SMEM);
    cudaFuncSetAttribute(k_embed_edges_mma, cudaFuncAttributeMaxDynamicSharedMemorySize, EB_SMEM);

    k_charge<<<64, 256>>>(charge, W_charge, b_charge);
    k_cvt_all<<<23, 256>>>(eu_W1, eu_b1, nu_W1, nu_b1, eu_W2, nu_W2, W_bond, W_atom);
    k_embed_nodes_mma<<<(NN + 127) / 128, 256, EN_SMEM>>>(x, batch, b_atom);
    k_embed_edges_mma<<<NT_EDGE, 256, EB_SMEM>>>(edge_attr, b_bond);

    for (int i = 0; i < LL; i++) {
        k_precompute<<<(NN + 127) / 128, 256, PRE_SMEM>>>(i, i > 0 ? 1 : 0);
        k_edge<<<444, 256, EDGE_SMEM>>>(eidx, i, eu_b2 + i * 64, nu_b2 + i * 64,
                                        i < LL - 1 ? 1 : 0);
        k_stats<<<STATS_BLOCKS, 256>>>(bn_g + i * 64, bn_b + i * 64);
    }
    k_update_pool<<<(NN * DD) / 256, 256>>>(batch);
    k_predict<<<GG, 128>>>(p_W1, p_b1, p_W2, p_b2, p_W3, p_b3, out);
}

// round 16
// speedup vs baseline: 1.0166x; 1.0026x over previous
#include <cuda_runtime.h>
#include <cuda_bf16.h>
#include <math.h>

#define NN 50000
#define EE 500000
#define GG 256
#define DD 64
#define LL 3
#define NT_EDGE ((EE + 127) / 128)
#define STATS_BLOCKS 256

// ------------------------------------------------------------------ globals
__device__ float    g_h[NN * DD];
__device__ unsigned g_ea[(size_t)EE * 32];      // bf16x2 words
__device__ unsigned g_Arh[NN * 32];             // bf16x2 gather tables
__device__ unsigned g_Ach[NN * 32];
__device__ unsigned g_Brh[NN * 32];
__device__ float    g_hnew[NN * DD];
__device__ double   g_stats[2 * DD];
__device__ unsigned g_stats_ctr;
__device__ float    g_ab[2 * DD];
__device__ float    g_pool[GG * DD];
__device__ float    g_cnt[GG];
__device__ float    g_cf[GG * 16];

__device__ unsigned g_wbond[64 * 36];           // hi-only
__device__ unsigned g_wpre[LL][192 * 36];       // hi-only
__device__ unsigned g_wehi[LL][4][64 * 36];     // hi-only
__device__ unsigned g_watom[2][64 * 68];        // hi+lo (fp32 output path)
__device__ float    g_bpre[LL][192];

__device__ __forceinline__ float sp_f(float x) {
    return x > 15.f ? x : __logf(1.f + __expf(x));
}
__device__ __forceinline__ int clampi(int v, int hi) {
    return v < 0 ? 0 : (v >= hi ? hi - 1 : v);
}
__device__ __forceinline__ unsigned pack2(float x, float y) {
    __nv_bfloat162 h = __floats2bfloat162_rn(x, y);
    return *reinterpret_cast<unsigned*>(&h);
}
__device__ __forceinline__ float2 up2(unsigned u) {
    __nv_bfloat162 h = *reinterpret_cast<__nv_bfloat162*>(&u);
    return __bfloat1622float2(h);
}
__device__ __forceinline__ void red4(float* a, float x, float y, float z, float w) {
    asm volatile("red.global.add.v4.f32 [%0], {%1,%2,%3,%4};"
                 :: "l"(a), "f"(x), "f"(y), "f"(z), "f"(w) : "memory");
}
__device__ __forceinline__ void mma_bf16(float& c0, float& c1, float& c2, float& c3,
                                         unsigned a0, unsigned a1, unsigned a2, unsigned a3,
                                         unsigned b0, unsigned b1) {
    asm volatile("mma.sync.aligned.m16n8k16.row.col.f32.bf16.bf16.f32 "
                 "{%0,%1,%2,%3}, {%4,%5,%6,%7}, {%8,%9}, {%0,%1,%2,%3};\n"
                 : "+f"(c0), "+f"(c1), "+f"(c2), "+f"(c3)
                 : "r"(a0), "r"(a1), "r"(a2), "r"(a3), "r"(b0), "r"(b1));
}

// hi+lo split-weight version (embed_nodes only)
template<int K0, int NT, int LD>
__device__ __forceinline__ void mma_tiles(const unsigned* sA, const unsigned* sWhi,
                                          const unsigned* sWlo, float acc[][NT][4],
                                          int wm, int wcol0, int gid, int tig) {
#pragma unroll
    for (int k0 = 0; k0 < K0; k0++) {
        unsigned a[2][4];
#pragma unroll
        for (int mt = 0; mt < 2; mt++) {
            const unsigned* base = &sA[(wm * 32 + mt * 16 + gid) * LD + k0 * 8 + tig];
            a[mt][0] = base[0];
            a[mt][1] = base[8 * LD];
            a[mt][2] = base[4];
            a[mt][3] = base[8 * LD + 4];
        }
#pragma unroll
        for (int nt = 0; nt < NT; nt++) {
            int off = (wcol0 + nt * 8 + gid) * LD + k0 * 8 + tig;
            unsigned bh0 = sWhi[off], bh1 = sWhi[off + 4];
            unsigned bl0 = sWlo[off], bl1 = sWlo[off + 4];
#pragma unroll
            for (int mt = 0; mt < 2; mt++) {
                mma_bf16(acc[mt][nt][0], acc[mt][nt][1], acc[mt][nt][2], acc[mt][nt][3],
                         a[mt][0], a[mt][1], a[mt][2], a[mt][3], bh0, bh1);
                mma_bf16(acc[mt][nt][0], acc[mt][nt][1], acc[mt][nt][2], acc[mt][nt][3],
                         a[mt][0], a[mt][1], a[mt][2], a[mt][3], bl0, bl1);
            }
        }
    }
}

// hi-only version
template<int K0, int NT, int LD>
__device__ __forceinline__ void mma_tiles_hi(const unsigned* sA, const unsigned* sWhi,
                                             float acc[][NT][4],
                                             int wm, int wcol0, int gid, int tig) {
#pragma unroll
    for (int k0 = 0; k0 < K0; k0++) {
        unsigned a[2][4];
#pragma unroll
        for (int mt = 0; mt < 2; mt++) {
            const unsigned* base = &sA[(wm * 32 + mt * 16 + gid) * LD + k0 * 8 + tig];
            a[mt][0] = base[0];
            a[mt][1] = base[8 * LD];
            a[mt][2] = base[4];
            a[mt][3] = base[8 * LD + 4];
        }
#pragma unroll
        for (int nt = 0; nt < NT; nt++) {
            int off = (wcol0 + nt * 8 + gid) * LD + k0 * 8 + tig;
            unsigned bh0 = sWhi[off], bh1 = sWhi[off + 4];
#pragma unroll
            for (int mt = 0; mt < 2; mt++)
                mma_bf16(acc[mt][nt][0], acc[mt][nt][1], acc[mt][nt][2], acc[mt][nt][3],
                         a[mt][0], a[mt][1], a[mt][2], a[mt][3], bh0, bh1);
        }
    }
}

// ------------------------------------------------------------------ one-time weight conversion
__global__ void k_cvt_all(const float* eu_W1, const float* eu_b1,
                          const float* nu_W1, const float* nu_b1,
                          const float* eu_W2, const float* nu_W2,
                          const float* W_bond, const float* W_atom) {
    int b = blockIdx.x, tid = threadIdx.x;
    if (b == 22) {   // W_atom: hi+lo
        __nv_bfloat16* hhi = reinterpret_cast<__nv_bfloat16*>(g_watom[0]);
        __nv_bfloat16* hlo = reinterpret_cast<__nv_bfloat16*>(g_watom[1]);
        for (int idx = tid; idx < 112 * 64; idx += 256) {
            int k = idx >> 6, n = idx & 63;
            float w = (k < 108) ? W_atom[k * 64 + n] : 0.f;
            __nv_bfloat16 hi = __float2bfloat16(w);
            float lo = w - __bfloat162float(hi);
            hhi[(size_t)n * 136 + k] = hi;
            hlo[(size_t)n * 136 + k] = __float2bfloat16(lo);
        }
        return;
    }
    const float* src; int i = 0, ncoff = 0, validK = 64;
    unsigned* dhi = 0;
    if (b == 0) {
        src = W_bond; validK = 41;
        dhi = g_wbond;
        for (int idx = tid; idx < LL * 192; idx += 256) {
            int ii = idx / 192, n = idx % 192;
            float v = 0.f;
            if (n < 64)        v = eu_b1[ii * 64 + n];
            else if (n >= 128) v = nu_b1[ii * 64 + (n - 128)];
            g_bpre[ii][n] = v;
        }
        if (tid == 0) g_stats_ctr = 0;
    } else {
        i = (b - 1) / 7; int j = (b - 1) % 7;
        const float* euW1 = eu_W1 + (size_t)i * 12288;
        const float* nuW1 = nu_W1 + (size_t)i * 8192;
        switch (j) {
            case 0: src = euW1;            dhi = g_wpre[i]; ncoff = 0;   break;
            case 1: src = euW1 + 4096;     dhi = g_wpre[i]; ncoff = 64;  break;
            case 2: src = nuW1;            dhi = g_wpre[i]; ncoff = 128; break;
            case 3: src = euW1 + 8192;     dhi = g_wehi[i][0]; break;
            case 4: src = eu_W2 + (size_t)i * 4096; dhi = g_wehi[i][1]; break;
            case 5: src = nuW1 + 4096;     dhi = g_wehi[i][2]; break;
            default: src = nu_W2 + (size_t)i * 4096; dhi = g_wehi[i][3]; break;
        }
    }
    __nv_bfloat16* hhi = reinterpret_cast<__nv_bfloat16*>(dhi);
    for (int idx = tid; idx < 4096; idx += 256) {
        int k = idx >> 6, n = idx & 63;
        float w = (k < validK) ? src[k * 64 + n] : 0.f;
        hhi[(size_t)(n + ncoff) * 72 + k] = __float2bfloat16(w);
    }
}

// ------------------------------------------------------------------ small kernels
__global__ void k_charge(const float* charge, const float* Wc, const float* bc) {
    int i = blockIdx.x * 256 + threadIdx.x;
    if (i < GG * 16) g_cf[i] = charge[i >> 4] * Wc[i & 15] + bc[i & 15];
    if (i < GG * DD) g_pool[i] = 0.f;
    if (i < GG) g_cnt[i] = 0.f;
}

// ------------------------------------------------------------------ node embedding via MMA (K=112)
__global__ __launch_bounds__(256) void k_embed_nodes_mma(
    const float* x, const int* batch, const float* b) {
    extern __shared__ unsigned dyn[];
    unsigned* sA = dyn;
    unsigned* sW = dyn + 128 * 68;
    int tid = threadIdx.x, n0 = blockIdx.x * 128;
    int warp = tid >> 5, lane = tid & 31;
    int wm = warp >> 1, wn = warp & 1;
    int gid = lane >> 2, tig = lane & 3;

    {
        const uint4* src = reinterpret_cast<const uint4*>(g_watom[0]);
        uint4* dst = reinterpret_cast<uint4*>(sW);
        for (int idx = tid; idx < 2 * 64 * 68 / 4; idx += 256) dst[idx] = src[idx];
    }
    for (int idx = tid; idx < 128 * 56; idx += 256) {
        int nr = idx / 56, kw = idx - nr * 56;
        int n = n0 + nr; if (n >= NN) n = NN - 1;
        int k = kw * 2;
        float v0, v1;
        int bb = clampi(batch[n], GG);
        v0 = (k < 92)      ? x[(size_t)n * 92 + k]
           : (k < 108)     ? g_cf[bb * 16 + (k - 92)] : 0.f;
        int k1 = k + 1;
        v1 = (k1 < 92)     ? x[(size_t)n * 92 + k1]
           : (k1 < 108)    ? g_cf[bb * 16 + (k1 - 92)] : 0.f;
        sA[nr * 68 + kw] = pack2(v0, v1);
    }
    __syncthreads();

    float acc[2][4][4];
#pragma unroll
    for (int mt = 0; mt < 2; mt++)
#pragma unroll
        for (int nt = 0; nt < 4; nt++) {
            float2 bv = *reinterpret_cast<const float2*>(&b[wn * 32 + nt * 8 + tig * 2]);
            acc[mt][nt][0] = bv.x; acc[mt][nt][1] = bv.y;
            acc[mt][nt][2] = bv.x; acc[mt][nt][3] = bv.y;
        }
    mma_tiles<7, 4, 68>(sA, sW, sW + 64 * 68, acc, wm, wn * 32, gid, tig);
#pragma unroll
    for (int mt = 0; mt < 2; mt++)
#pragma unroll
        for (int nt = 0; nt < 4; nt++) {
            int row = wm * 32 + mt * 16 + gid;
            int col = wn * 32 + nt * 8 + tig * 2;
            int n = n0 + row;
            if (n < NN)
                *reinterpret_cast<float2*>(&g_h[(size_t)n * 64 + col]) =
                    make_float2(acc[mt][nt][0], acc[mt][nt][1]);
            if (n + 8 < NN)
                *reinterpret_cast<float2*>(&g_h[(size_t)(n + 8) * 64 + col]) =
                    make_float2(acc[mt][nt][2], acc[mt][nt][3]);
        }
}

// ------------------------------------------------------------------ edge embedding (hi-only, plain loads)
__global__ __launch_bounds__(256) void k_embed_edges_mma(const float* ea, const float* b) {
    extern __shared__ float dynf[];
    float*    flat = dynf;                               // 128*41
    unsigned* sA   = reinterpret_cast<unsigned*>(dynf + 5248);
    unsigned* sW   = sA + 128 * 36;                      // 64*36 hi only
    int tid = threadIdx.x, e0 = blockIdx.x * 128;
    int warp = tid >> 5, lane = tid & 31;
    int wm = warp >> 1, wn = warp & 1;
    int gid = lane >> 2, tig = lane & 3;

    {
        const uint4* src = reinterpret_cast<const uint4*>(g_wbond);
        uint4* dst = reinterpret_cast<uint4*>(sW);
        for (int idx = tid; idx < 64 * 36 / 4; idx += 256) dst[idx] = src[idx];
    }
    int valid = EE - e0; if (valid > 128) valid = 128;
    int nload = valid * 41;
    for (int idx = tid; idx < nload; idx += 256)
        flat[idx] = ea[(size_t)e0 * 41 + idx];
    __syncthreads();
    for (int idx = tid; idx < 128 * 24; idx += 256) {
        int er = idx / 24, kw = idx - er * 24;
        int k = kw * 2;
        float v0 = 0.f, v1 = 0.f;
        if (er < valid) {
            if (k < 41)     v0 = flat[er * 41 + k];
            if (k + 1 < 41) v1 = flat[er * 41 + k + 1];
        }
        sA[er * 36 + kw] = pack2(v0, v1);
    }
    __syncthreads();

    float acc[2][4][4];
#pragma unroll
    for (int mt = 0; mt < 2; mt++)
#pragma unroll
        for (int nt = 0; nt < 4; nt++) {
            float2 bv = *reinterpret_cast<const float2*>(&b[wn * 32 + nt * 8 + tig * 2]);
            acc[mt][nt][0] = bv.x; acc[mt][nt][1] = bv.y;
            acc[mt][nt][2] = bv.x; acc[mt][nt][3] = bv.y;
        }
    mma_tiles_hi<3, 4, 36>(sA, sW, acc, wm, wn * 32, gid, tig);
#pragma unroll
    for (int mt = 0; mt < 2; mt++)
#pragma unroll
        for (int nt = 0; nt < 4; nt++) {
            int row = wm * 32 + mt * 16 + gid;
            int cw = wn * 16 + nt * 4 + tig;
            int e = e0 + row;
            if (e < EE)     g_ea[(size_t)e * 32 + cw]       = pack2(acc[mt][nt][0], acc[mt][nt][1]);
            if (e + 8 < EE) g_ea[(size_t)(e + 8) * 32 + cw] = pack2(acc[mt][nt][2], acc[mt][nt][3]);
        }
}

// ------------------------------------------------------------------ fused precompute (+ BN/update of previous layer)
__global__ __launch_bounds__(256) void k_precompute(int layer, int do_update) {
    extern __shared__ unsigned dyn[];
    unsigned* sA = dyn;                       // 128*36
    unsigned* sW = dyn + 128 * 36;            // 192*36 hi only
    int tid = threadIdx.x, n0 = blockIdx.x * 128;
    int warp = tid >> 5, lane = tid & 31;
    int wm = warp >> 1, wn = warp & 1;
    int gid = lane >> 2, tig = lane & 3;

    {
        const uint4* src = reinterpret_cast<const uint4*>(g_wpre[layer]);
        uint4* dst = reinterpret_cast<uint4*>(sW);
        for (int idx = tid; idx < 192 * 36 / 4; idx += 256) dst[idx] = src[idx];
    }
    for (int idx = tid; idx < 128 * 32; idx += 256) {
        int nr = idx >> 5, cw = idx & 31;
        int n = n0 + nr;
        if (n < NN) {
            size_t off = (size_t)n * 64 + cw * 2;
            float2 h = *reinterpret_cast<const float2*>(&g_h[off]);
            if (do_update) {
                float2 hn = *reinterpret_cast<const float2*>(&g_hnew[off]);
                int j = cw * 2;
                h.x = sp_f(hn.x * g_ab[j]     + g_ab[64 + j])     + h.x;
                h.y = sp_f(hn.y * g_ab[j + 1] + g_ab[64 + j + 1]) + h.y;
                *reinterpret_cast<float2*>(&g_h[off]) = h;
            }
            sA[nr * 36 + cw] = pack2(h.x, h.y);
            *reinterpret_cast<float2*>(&g_hnew[off]) = make_float2(0.f, 0.f);
        } else sA[nr * 36 + cw] = 0u;
    }
    __syncthreads();

    float acc[2][12][4];
#pragma unroll
    for (int mt = 0; mt < 2; mt++)
#pragma unroll
        for (int nt = 0; nt < 12; nt++) {
            int nc = wn * 96 + nt * 8 + tig * 2;
            float2 bv = *reinterpret_cast<const float2*>(&g_bpre[layer][nc]);
            acc[mt][nt][0] = bv.x; acc[mt][nt][1] = bv.y;
            acc[mt][nt][2] = bv.x; acc[mt][nt][3] = bv.y;
        }
    mma_tiles_hi<4, 12, 36>(sA, sW, acc, wm, wn * 96, gid, tig);
#pragma unroll
    for (int mt = 0; mt < 2; mt++)
#pragma unroll
        for (int nt = 0; nt < 12; nt++) {
            int nc = wn * 96 + nt * 8 + tig * 2;
            unsigned* O = nc < 64 ? g_Arh : (nc < 128 ? g_Ach : g_Brh);
            int cw = (nc & 63) >> 1;
            int row = wm * 32 + mt * 16 + gid;
            int n = n0 + row;
            if (n < NN)     O[(size_t)n * 32 + cw]       = pack2(acc[mt][nt][0], acc[mt][nt][1]);
            if (n + 8 < NN) O[(size_t)(n + 8) * 32 + cw] = pack2(acc[mt][nt][2], acc[mt][nt][3]);
        }
}

// ------------------------------------------------------------------ fused edge pipeline (R13 config, red4 scatter)
__global__ __launch_bounds__(256, 3) void k_edge(const int* eidx, int layer,
                                                 const float* b2, const float* b4,
                                                 int store_ea) {
    extern __shared__ unsigned dyn[];
    unsigned* sA = dyn;                    // 128*36
    unsigned* sW = dyn + 128 * 36;         // 4 stages * 2304
    __shared__ float sB2[64], sB4[64];
    __shared__ int sRow[128], sCol[128];

    int tid = threadIdx.x;
    int warp = tid >> 5, lane = tid & 31;
    int wm = warp >> 1, wn = warp & 1;
    int gid = lane >> 2, tig = lane & 3;

    if (tid < 64) { sB2[tid] = b2[tid]; sB4[tid] = b4[tid]; }
    {
        const uint4* src = reinterpret_cast<const uint4*>(&g_wehi[layer][0][0]);
        uint4* dst = reinterpret_cast<uint4*>(sW);
        for (int idx = tid; idx < 4 * 2304 / 4; idx += 256) dst[idx] = src[idx];
    }
    const unsigned* W1h = sW;
    const unsigned* W2h = sW + 2304;
    const unsigned* W3h = sW + 4608;
    const unsigned* W4h = sW + 6912;

    for (int t = blockIdx.x; t < NT_EDGE; t += gridDim.x) {
        int e0 = t * 128;
        __syncthreads();
        if (tid < 128) {
            int e = e0 + tid; if (e >= EE) e = EE - 1;
            sRow[tid] = clampi(eidx[e], NN);
            sCol[tid] = clampi(eidx[EE + e], NN);
        }
        for (int idx = tid; idx < 128 * 32; idx += 256) {
            int er = idx >> 5, cw = idx & 31;
            int e = e0 + er; if (e >= EE) e = EE - 1;
            sA[er * 36 + cw] = g_ea[(size_t)e * 32 + cw];
        }
        __syncthreads();

        float acc[2][4][4];

        // ---- stage 1
#pragma unroll
        for (int mt = 0; mt < 2; mt++)
#pragma unroll
            for (int nt = 0; nt < 4; nt++) {
                int row = wm * 32 + mt * 16 + gid;
                int cw = wn * 16 + nt * 4 + tig;
                float2 a0 = up2(g_Arh[(size_t)sRow[row] * 32 + cw]);
                float2 q0 = up2(g_Ach[(size_t)sCol[row] * 32 + cw]);
                float2 a1 = up2(g_Arh[(size_t)sRow[row + 8] * 32 + cw]);
                float2 q1 = up2(g_Ach[(size_t)sCol[row + 8] * 32 + cw]);
                acc[mt][nt][0] = a0.x + q0.x; acc[mt][nt][1] = a0.y + q0.y;
                acc[mt][nt][2] = a1.x + q1.x; acc[mt][nt][3] = a1.y + q1.y;
            }
        mma_tiles_hi<4, 4, 36>(sA, W1h, acc, wm, wn * 32, gid, tig);
        __syncthreads();
#pragma unroll
        for (int mt = 0; mt < 2; mt++)
#pragma unroll
            for (int nt = 0; nt < 4; nt++) {
                int row = wm * 32 + mt * 16 + gid;
                int cw = wn * 16 + nt * 4 + tig;
                sA[row * 36 + cw]       = pack2(sp_f(acc[mt][nt][0]), sp_f(acc[mt][nt][1]));
                sA[(row + 8) * 36 + cw] = pack2(sp_f(acc[mt][nt][2]), sp_f(acc[mt][nt][3]));
            }
        __syncthreads();

        // ---- stage 2
#pragma unroll
        for (int mt = 0; mt < 2; mt++)
#pragma unroll
            for (int nt = 0; nt < 4; nt++) {
                int col = wn * 32 + nt * 8 + tig * 2;
                float2 bv = *reinterpret_cast<const float2*>(&sB2[col]);
                acc[mt][nt][0] = bv.x; acc[mt][nt][1] = bv.y;
                acc[mt][nt][2] = bv.x; acc[mt][nt][3] = bv.y;
            }
        mma_tiles_hi<4, 4, 36>(sA, W2h, acc, wm, wn * 32, gid, tig);
        __syncthreads();
#pragma unroll
        for (int mt = 0; mt < 2; mt++)
#pragma unroll
            for (int nt = 0; nt < 4; nt++) {
                int row = wm * 32 + mt * 16 + gid;
                int cw = wn * 16 + nt * 4 + tig;
                unsigned p0 = pack2(acc[mt][nt][0], acc[mt][nt][1]);
                unsigned p1 = pack2(acc[mt][nt][2], acc[mt][nt][3]);
                sA[row * 36 + cw]       = p0;
                sA[(row + 8) * 36 + cw] = p1;
                if (store_ea) {
                    int e = e0 + row;
                    if (e < EE)     g_ea[(size_t)e * 32 + cw]       = p0;
                    if (e + 8 < EE) g_ea[(size_t)(e + 8) * 32 + cw] = p1;
                }
            }
        __syncthreads();

        // ---- stage 3
#pragma unroll
        for (int mt = 0; mt < 2; mt++)
#pragma unroll
            for (int nt = 0; nt < 4; nt++) {
                int row = wm * 32 + mt * 16 + gid;
                int cw = wn * 16 + nt * 4 + tig;
                float2 v0 = up2(g_Brh[(size_t)sRow[row] * 32 + cw]);
                float2 v1 = up2(g_Brh[(size_t)sRow[row + 8] * 32 + cw]);
                acc[mt][nt][0] = v0.x; acc[mt][nt][1] = v0.y;
                acc[mt][nt][2] = v1.x; acc[mt][nt][3] = v1.y;
            }
        mma_tiles_hi<4, 4, 36>(sA, W3h, acc, wm, wn * 32, gid, tig);
        __syncthreads();
#pragma unroll
        for (int mt = 0; mt < 2; mt++)
#pragma unroll
            for (int nt = 0; nt < 4; nt++) {
                int row = wm * 32 + mt * 16 + gid;
                int cw = wn * 16 + nt * 4 + tig;
                sA[row * 36 + cw]       = pack2(sp_f(acc[mt][nt][0]), sp_f(acc[mt][nt][1]));
                sA[(row + 8) * 36 + cw] = pack2(sp_f(acc[mt][nt][2]), sp_f(acc[mt][nt][3]));
            }
        __syncthreads();

        // ---- stage 4 -> vectorized red4 scatter (lane pairing via shuffle)
#pragma unroll
        for (int mt = 0; mt < 2; mt++)
#pragma unroll
            for (int nt = 0; nt < 4; nt++) {
                int col = wn * 32 + nt * 8 + tig * 2;
                float2 bv = *reinterpret_cast<const float2*>(&sB4[col]);
                acc[mt][nt][0] = bv.x; acc[mt][nt][1] = bv.y;
                acc[mt][nt][2] = bv.x; acc[mt][nt][3] = bv.y;
            }
        mma_tiles_hi<4, 4, 36>(sA, W4h, acc, wm, wn * 32, gid, tig);
#pragma unroll
        for (int mt = 0; mt < 2; mt++)
#pragma unroll
            for (int nt = 0; nt < 4; nt++) {
                // even tig lanes merge with tig+1's pair -> one 16B red4 per row
                float p0 = __shfl_down_sync(0xffffffff, acc[mt][nt][0], 1);
                float p1 = __shfl_down_sync(0xffffffff, acc[mt][nt][1], 1);
                float p2 = __shfl_down_sync(0xffffffff, acc[mt][nt][2], 1);
                float p3 = __shfl_down_sync(0xffffffff, acc[mt][nt][3], 1);
                if ((tig & 1) == 0) {
                    int row = wm * 32 + mt * 16 + gid;
                    int colb = wn * 32 + nt * 8 + (tig & 2) * 2;   // 16B aligned
                    int e = e0 + row;
                    if (e < EE)
                        red4(&g_hnew[(size_t)sCol[row] * 64 + colb],
                             acc[mt][nt][0], acc[mt][nt][1], p0, p1);
                    if (e + 8 < EE)
                        red4(&g_hnew[(size_t)sCol[row + 8] * 64 + colb],
                             acc[mt][nt][2], acc[mt][nt][3], p2, p3);
                }
            }
    }
}

// ------------------------------------------------------------------ stats + fused finalize (last block)
__global__ void k_stats(const float* gamma, const float* beta) {
    int c = threadIdx.x & 63, rr = threadIdx.x >> 6;
    int tid = threadIdx.x;
    double s = 0.0, s2 = 0.0;
    for (int n = blockIdx.x * 4 + rr; n < NN; n += gridDim.x * 4) {
        float v = g_hnew[n * 64 + c];
        s += v; s2 += (double)v * v;
    }
    __shared__ double sh[8][64];
    __shared__ int isLast;
    sh[rr][c] = s; sh[4 + rr][c] = s2;
    __syncthreads();
    if (rr == 0) {
        atomicAdd(&g_stats[c],      sh[0][c] + sh[1][c] + sh[2][c] + sh[3][c]);
        atomicAdd(&g_stats[64 + c], sh[4][c] + sh[5][c] + sh[6][c] + sh[7][c]);
    }
    if (tid == 0) {
        __threadfence();
        unsigned done = atomicAdd(&g_stats_ctr, 1u);
        isLast = (done == (unsigned)(gridDim.x - 1));
    }
    __syncthreads();
    if (isLast) {
        if (tid == 0) g_stats_ctr = 0;
        if (tid < 64) {
            double mu = g_stats[tid] / (double)NN;
            double var = g_stats[64 + tid] / (double)NN - mu * mu;
            float a = rsqrtf((float)var + 1e-5f) * gamma[tid];
            g_ab[tid] = a;
            g_ab[64 + tid] = beta[tid] - (float)mu * a;
            g_stats[tid] = 0.0;                    // reset for next layer
            g_stats[64 + tid] = 0.0;
        }
    }
}

__global__ void k_update_pool(const int* batch) {
    int idx = blockIdx.x * 256 + threadIdx.x;
    int j = idx & 63;
    float v = g_hnew[idx] * g_ab[j] + g_ab[64 + j];
    float h = sp_f(v) + g_h[idx];
    int b = clampi(batch[idx >> 6], GG);
    atomicAdd(&g_pool[b * 64 + j], h);
    if (j == 0) atomicAdd(&g_cnt[b], 1.f);
}

__global__ void k_predict(const float* W1, const float* b1,
                          const float* W2, const float* b2,
                          const float* W3, const float* b3, float* out) {
    __shared__ float gr[64], z1[128], z2[128];
    __shared__ float red[4];
    int g = blockIdx.x, t = threadIdx.x;
    if (t < 64) gr[t] = g_pool[g * 64 + t] / fmaxf(g_cnt[g], 1.f);
    __syncthreads();
    float acc = b1[t];
    for (int k = 0; k < 64; k++) acc = fmaf(gr[k], W1[k * 128 + t], acc);
    z1[t] = sp_f(acc);
    __syncthreads();
    acc = b2[t];
    for (int k = 0; k < 128; k++) acc = fmaf(z1[k], W2[k * 128 + t], acc);
    z2[t] = sp_f(acc);
    __syncthreads();
    float v = z2[t] * W3[t];
    for (int o = 16; o > 0; o >>= 1) v += __shfl_down_sync(0xffffffff, v, o);
    if ((t & 31) == 0) red[t >> 5] = v;
    __syncthreads();
    if (t == 0) out[g] = red[0] + red[1] + red[2] + red[3] + b3[0];
}

// ------------------------------------------------------------------ launch
extern "C" void kernel_launch(void* const* d_in, const int* in_sizes, int n_in,
                              void* d_out, int out_size) {
    const float* x         = (const float*)d_in[0];
    const float* edge_attr = (const float*)d_in[1];
    const float* charge    = (const float*)d_in[2];
    const int*   eidx      = (const int*)d_in[3];
    const int*   batch     = (const int*)d_in[4];
    const float* W_charge  = (const float*)d_in[5];
    const float* b_charge  = (const float*)d_in[6];
    const float* W_atom    = (const float*)d_in[7];
    const float* b_atom    = (const float*)d_in[8];
    const float* W_bond    = (const float*)d_in[9];
    const float* b_bond    = (const float*)d_in[10];
    const float* nu_W1     = (const float*)d_in[11];
    const float* nu_b1     = (const float*)d_in[12];
    const float* nu_W2     = (const float*)d_in[13];
    const float* nu_b2     = (const float*)d_in[14];
    const float* eu_W1     = (const float*)d_in[15];
    const float* eu_b1     = (const float*)d_in[16];
    const float* eu_W2     = (const float*)d_in[17];
    const float* eu_b2     = (const float*)d_in[18];
    const float* bn_g      = (const float*)d_in[19];
    const float* bn_b      = (const float*)d_in[20];
    const float* p_W1      = (const float*)d_in[21];
    const float* p_b1      = (const float*)d_in[22];
    const float* p_W2      = (const float*)d_in[23];
    const float* p_b2      = (const float*)d_in[24];
    const float* p_W3      = (const float*)d_in[25];
    const float* p_b3      = (const float*)d_in[26];
    float* out = (float*)d_out;

    const int PRE_SMEM  = (128 * 36 + 192 * 36) * 4;           // 46080
    const int EDGE_SMEM = (128 * 36 + 4 * 2304) * 4;           // 55296
    const int EN_SMEM   = (128 * 68 + 2 * 64 * 68) * 4;        // 69632
    const int EB_SMEM   = (5248 + 128 * 36 + 64 * 36) * 4;     // 48640
    cudaFuncSetAttribute(k_precompute, cudaFuncAttributeMaxDynamicSharedMemorySize, PRE_SMEM);
    cudaFuncSetAttribute(k_edge, cudaFuncAttributeMaxDynamicSharedMemorySize, EDGE_SMEM);
    cudaFuncSetAttribute(k_embed_nodes_mma, cudaFuncAttributeMaxDynamicSharedMemorySize, EN_SMEM);
    cudaFuncSetAttribute(k_embed_edges_mma, cudaFuncAttributeMaxDynamicSharedMemorySize, EB_SMEM);

    k_charge<<<64, 256>>>(charge, W_charge, b_charge);
    k_cvt_all<<<23, 256>>>(eu_W1, eu_b1, nu_W1, nu_b1, eu_W2, nu_W2, W_bond, W_atom);
    k_embed_nodes_mma<<<(NN + 127) / 128, 256, EN_SMEM>>>(x, batch, b_atom);
    k_embed_edges_mma<<<NT_EDGE, 256, EB_SMEM>>>(edge_attr, b_bond);

    for (int i = 0; i < LL; i++) {
        k_precompute<<<(NN + 127) / 128, 256, PRE_SMEM>>>(i, i > 0 ? 1 : 0);
        k_edge<<<444, 256, EDGE_SMEM>>>(eidx, i, eu_b2 + i * 64, nu_b2 + i * 64,
                                        i < LL - 1 ? 1 : 0);
        k_stats<<<STATS_BLOCKS, 256>>>(bn_g + i * 64, bn_b + i * 64);
    }
    k_update_pool<<<(NN * DD) / 256, 256>>>(batch);
    k_predict<<<GG, 128>>>(p_W1, p_b1, p_W2, p_b2, p_W3, p_b3, out);
}

// round 17
// speedup vs baseline: 1.1020x; 1.0840x over previous
#include <cuda_runtime.h>
#include <cuda_bf16.h>
#include <math.h>

#define NN 50000
#define EE 500000
#define GG 256
#define DD 64
#define LL 3
#define NT_EDGE ((EE + 127) / 128)

// ------------------------------------------------------------------ globals
__device__ float    g_h[NN * DD];
__device__ unsigned g_ea[(size_t)EE * 32];      // bf16x2 words
__device__ unsigned g_Arh[NN * 32];             // bf16x2 gather tables
__device__ unsigned g_Ach[NN * 32];
__device__ unsigned g_Brh[NN * 32];
__device__ float    g_hnew[NN * DD];
__device__ double   g_stats[2 * DD];
__device__ float    g_ab[2 * DD];
__device__ float    g_pool[GG * DD];
__device__ float    g_cnt[GG];
__device__ float    g_cf[GG * 16];

__device__ unsigned g_wbond[64 * 36];           // hi-only
__device__ unsigned g_wpre[LL][192 * 36];       // hi-only
__device__ unsigned g_wehi[LL][4][64 * 36];     // hi-only
__device__ unsigned g_watom[2][64 * 68];        // hi+lo (fp32 output path)
__device__ float    g_bpre[LL][192];

__device__ __forceinline__ float sp_f(float x) {
    return x > 15.f ? x : __logf(1.f + __expf(x));
}
__device__ __forceinline__ int clampi(int v, int hi) {
    return v < 0 ? 0 : (v >= hi ? hi - 1 : v);
}
__device__ __forceinline__ unsigned pack2(float x, float y) {
    __nv_bfloat162 h = __floats2bfloat162_rn(x, y);
    return *reinterpret_cast<unsigned*>(&h);
}
__device__ __forceinline__ float2 up2(unsigned u) {
    __nv_bfloat162 h = *reinterpret_cast<__nv_bfloat162*>(&u);
    return __bfloat1622float2(h);
}
__device__ __forceinline__ void red2(float* a, float x, float y) {
    asm volatile("red.global.add.v2.f32 [%0], {%1,%2};" :: "l"(a), "f"(x), "f"(y) : "memory");
}
__device__ __forceinline__ void pair_bar(int pm) {
    asm volatile("bar.sync %0, 64;" :: "r"(pm + 1) : "memory");
}
__device__ __forceinline__ void mma_bf16(float& c0, float& c1, float& c2, float& c3,
                                         unsigned a0, unsigned a1, unsigned a2, unsigned a3,
                                         unsigned b0, unsigned b1) {
    asm volatile("mma.sync.aligned.m16n8k16.row.col.f32.bf16.bf16.f32 "
                 "{%0,%1,%2,%3}, {%4,%5,%6,%7}, {%8,%9}, {%0,%1,%2,%3};\n"
                 : "+f"(c0), "+f"(c1), "+f"(c2), "+f"(c3)
                 : "r"(a0), "r"(a1), "r"(a2), "r"(a3), "r"(b0), "r"(b1));
}

// hi+lo split-weight version (embed_nodes only)
template<int K0, int NT, int LD>
__device__ __forceinline__ void mma_tiles(const unsigned* sA, const unsigned* sWhi,
                                          const unsigned* sWlo, float acc[][NT][4],
                                          int wm, int wcol0, int gid, int tig) {
#pragma unroll
    for (int k0 = 0; k0 < K0; k0++) {
        unsigned a[2][4];
#pragma unroll
        for (int mt = 0; mt < 2; mt++) {
            const unsigned* base = &sA[(wm * 32 + mt * 16 + gid) * LD + k0 * 8 + tig];
            a[mt][0] = base[0];
            a[mt][1] = base[8 * LD];
            a[mt][2] = base[4];
            a[mt][3] = base[8 * LD + 4];
        }
#pragma unroll
        for (int nt = 0; nt < NT; nt++) {
            int off = (wcol0 + nt * 8 + gid) * LD + k0 * 8 + tig;
            unsigned bh0 = sWhi[off], bh1 = sWhi[off + 4];
            unsigned bl0 = sWlo[off], bl1 = sWlo[off + 4];
#pragma unroll
            for (int mt = 0; mt < 2; mt++) {
                mma_bf16(acc[mt][nt][0], acc[mt][nt][1], acc[mt][nt][2], acc[mt][nt][3],
                         a[mt][0], a[mt][1], a[mt][2], a[mt][3], bh0, bh1);
                mma_bf16(acc[mt][nt][0], acc[mt][nt][1], acc[mt][nt][2], acc[mt][nt][3],
                         a[mt][0], a[mt][1], a[mt][2], a[mt][3], bl0, bl1);
            }
        }
    }
}

// hi-only version
template<int K0, int NT, int LD>
__device__ __forceinline__ void mma_tiles_hi(const unsigned* sA, const unsigned* sWhi,
                                             float acc[][NT][4],
                                             int wm, int wcol0, int gid, int tig) {
#pragma unroll
    for (int k0 = 0; k0 < K0; k0++) {
        unsigned a[2][4];
#pragma unroll
        for (int mt = 0; mt < 2; mt++) {
            const unsigned* base = &sA[(wm * 32 + mt * 16 + gid) * LD + k0 * 8 + tig];
            a[mt][0] = base[0];
            a[mt][1] = base[8 * LD];
            a[mt][2] = base[4];
            a[mt][3] = base[8 * LD + 4];
        }
#pragma unroll
        for (int nt = 0; nt < NT; nt++) {
            int off = (wcol0 + nt * 8 + gid) * LD + k0 * 8 + tig;
            unsigned bh0 = sWhi[off], bh1 = sWhi[off + 4];
#pragma unroll
            for (int mt = 0; mt < 2; mt++)
                mma_bf16(acc[mt][nt][0], acc[mt][nt][1], acc[mt][nt][2], acc[mt][nt][3],
                         a[mt][0], a[mt][1], a[mt][2], a[mt][3], bh0, bh1);
        }
    }
}

// ------------------------------------------------------------------ one-time weight conversion
__global__ void k_cvt_all(const float* eu_W1, const float* eu_b1,
                          const float* nu_W1, const float* nu_b1,
                          const float* eu_W2, const float* nu_W2,
                          const float* W_bond, const float* W_atom) {
    int b = blockIdx.x, tid = threadIdx.x;
    if (b == 22) {   // W_atom: hi+lo
        __nv_bfloat16* hhi = reinterpret_cast<__nv_bfloat16*>(g_watom[0]);
        __nv_bfloat16* hlo = reinterpret_cast<__nv_bfloat16*>(g_watom[1]);
        for (int idx = tid; idx < 112 * 64; idx += 256) {
            int k = idx >> 6, n = idx & 63;
            float w = (k < 108) ? W_atom[k * 64 + n] : 0.f;
            __nv_bfloat16 hi = __float2bfloat16(w);
            float lo = w - __bfloat162float(hi);
            hhi[(size_t)n * 136 + k] = hi;
            hlo[(size_t)n * 136 + k] = __float2bfloat16(lo);
        }
        return;
    }
    const float* src; int i = 0, ncoff = 0, validK = 64;
    unsigned* dhi = 0;
    if (b == 0) {
        src = W_bond; validK = 41;
        dhi = g_wbond;
        for (int idx = tid; idx < LL * 192; idx += 256) {
            int ii = idx / 192, n = idx % 192;
            float v = 0.f;
            if (n < 64)        v = eu_b1[ii * 64 + n];
            else if (n >= 128) v = nu_b1[ii * 64 + (n - 128)];
            g_bpre[ii][n] = v;
        }
    } else {
        i = (b - 1) / 7; int j = (b - 1) % 7;
        const float* euW1 = eu_W1 + (size_t)i * 12288;
        const float* nuW1 = nu_W1 + (size_t)i * 8192;
        switch (j) {
            case 0: src = euW1;            dhi = g_wpre[i]; ncoff = 0;   break;
            case 1: src = euW1 + 4096;     dhi = g_wpre[i]; ncoff = 64;  break;
            case 2: src = nuW1;            dhi = g_wpre[i]; ncoff = 128; break;
            case 3: src = euW1 + 8192;     dhi = g_wehi[i][0]; break;
            case 4: src = eu_W2 + (size_t)i * 4096; dhi = g_wehi[i][1]; break;
            case 5: src = nuW1 + 4096;     dhi = g_wehi[i][2]; break;
            default: src = nu_W2 + (size_t)i * 4096; dhi = g_wehi[i][3]; break;
        }
    }
    __nv_bfloat16* hhi = reinterpret_cast<__nv_bfloat16*>(dhi);
    for (int idx = tid; idx < 4096; idx += 256) {
        int k = idx >> 6, n = idx & 63;
        float w = (k < validK) ? src[k * 64 + n] : 0.f;
        hhi[(size_t)(n + ncoff) * 72 + k] = __float2bfloat16(w);
    }
}

// ------------------------------------------------------------------ small kernels
__global__ void k_charge(const float* charge, const float* Wc, const float* bc) {
    int i = blockIdx.x * 256 + threadIdx.x;
    if (i < GG * 16) g_cf[i] = charge[i >> 4] * Wc[i & 15] + bc[i & 15];
    if (i < GG * DD) g_pool[i] = 0.f;
    if (i < GG) g_cnt[i] = 0.f;
}

// ------------------------------------------------------------------ node embedding via MMA (K=112)
__global__ __launch_bounds__(256) void k_embed_nodes_mma(
    const float* x, const int* batch, const float* b) {
    extern __shared__ unsigned dyn[];
    unsigned* sA = dyn;
    unsigned* sW = dyn + 128 * 68;
    int tid = threadIdx.x, n0 = blockIdx.x * 128;
    int warp = tid >> 5, lane = tid & 31;
    int wm = warp >> 1, wn = warp & 1;
    int gid = lane >> 2, tig = lane & 3;

    {
        const uint4* src = reinterpret_cast<const uint4*>(g_watom[0]);
        uint4* dst = reinterpret_cast<uint4*>(sW);
        for (int idx = tid; idx < 2 * 64 * 68 / 4; idx += 256) dst[idx] = src[idx];
    }
    for (int idx = tid; idx < 128 * 56; idx += 256) {
        int nr = idx / 56, kw = idx - nr * 56;
        int n = n0 + nr; if (n >= NN) n = NN - 1;
        int k = kw * 2;
        float v0, v1;
        int bb = clampi(batch[n], GG);
        v0 = (k < 92)      ? x[(size_t)n * 92 + k]
           : (k < 108)     ? g_cf[bb * 16 + (k - 92)] : 0.f;
        int k1 = k + 1;
        v1 = (k1 < 92)     ? x[(size_t)n * 92 + k1]
           : (k1 < 108)    ? g_cf[bb * 16 + (k1 - 92)] : 0.f;
        sA[nr * 68 + kw] = pack2(v0, v1);
    }
    __syncthreads();

    float acc[2][4][4];
#pragma unroll
    for (int mt = 0; mt < 2; mt++)
#pragma unroll
        for (int nt = 0; nt < 4; nt++) {
            float2 bv = *reinterpret_cast<const float2*>(&b[wn * 32 + nt * 8 + tig * 2]);
            acc[mt][nt][0] = bv.x; acc[mt][nt][1] = bv.y;
            acc[mt][nt][2] = bv.x; acc[mt][nt][3] = bv.y;
        }
    mma_tiles<7, 4, 68>(sA, sW, sW + 64 * 68, acc, wm, wn * 32, gid, tig);
#pragma unroll
    for (int mt = 0; mt < 2; mt++)
#pragma unroll
        for (int nt = 0; nt < 4; nt++) {
            int row = wm * 32 + mt * 16 + gid;
            int col = wn * 32 + nt * 8 + tig * 2;
            int n = n0 + row;
            if (n < NN)
                *reinterpret_cast<float2*>(&g_h[(size_t)n * 64 + col]) =
                    make_float2(acc[mt][nt][0], acc[mt][nt][1]);
            if (n + 8 < NN)
                *reinterpret_cast<float2*>(&g_h[(size_t)(n + 8) * 64 + col]) =
                    make_float2(acc[mt][nt][2], acc[mt][nt][3]);
        }
}

// ------------------------------------------------------------------ edge embedding (hi-only)
__global__ __launch_bounds__(256) void k_embed_edges_mma(const float* ea, const float* b) {
    extern __shared__ float dynf[];
    float*    flat = dynf;                               // 128*41
    unsigned* sA   = reinterpret_cast<unsigned*>(dynf + 5248);
    unsigned* sW   = sA + 128 * 36;                      // 64*36 hi only
    int tid = threadIdx.x, e0 = blockIdx.x * 128;
    int warp = tid >> 5, lane = tid & 31;
    int wm = warp >> 1, wn = warp & 1;
    int gid = lane >> 2, tig = lane & 3;

    {
        const uint4* src = reinterpret_cast<const uint4*>(g_wbond);
        uint4* dst = reinterpret_cast<uint4*>(sW);
        for (int idx = tid; idx < 64 * 36 / 4; idx += 256) dst[idx] = src[idx];
    }
    int valid = EE - e0; if (valid > 128) valid = 128;
    int nload = valid * 41;
    for (int idx = tid; idx < nload; idx += 256)
        flat[idx] = ea[(size_t)e0 * 41 + idx];
    __syncthreads();
    for (int idx = tid; idx < 128 * 24; idx += 256) {
        int er = idx / 24, kw = idx - er * 24;
        int k = kw * 2;
        float v0 = 0.f, v1 = 0.f;
        if (er < valid) {
            if (k < 41)     v0 = flat[er * 41 + k];
            if (k + 1 < 41) v1 = flat[er * 41 + k + 1];
        }
        sA[er * 36 + kw] = pack2(v0, v1);
    }
    __syncthreads();

    float acc[2][4][4];
#pragma unroll
    for (int mt = 0; mt < 2; mt++)
#pragma unroll
        for (int nt = 0; nt < 4; nt++) {
            float2 bv = *reinterpret_cast<const float2*>(&b[wn * 32 + nt * 8 + tig * 2]);
            acc[mt][nt][0] = bv.x; acc[mt][nt][1] = bv.y;
            acc[mt][nt][2] = bv.x; acc[mt][nt][3] = bv.y;
        }
    mma_tiles_hi<3, 4, 36>(sA, sW, acc, wm, wn * 32, gid, tig);
#pragma unroll
    for (int mt = 0; mt < 2; mt++)
#pragma unroll
        for (int nt = 0; nt < 4; nt++) {
            int row = wm * 32 + mt * 16 + gid;
            int cw = wn * 16 + nt * 4 + tig;
            int e = e0 + row;
            if (e < EE)     g_ea[(size_t)e * 32 + cw]       = pack2(acc[mt][nt][0], acc[mt][nt][1]);
            if (e + 8 < EE) g_ea[(size_t)(e + 8) * 32 + cw] = pack2(acc[mt][nt][2], acc[mt][nt][3]);
        }
}

// ------------------------------------------------------------------ fused precompute (+ BN/update of previous layer)
__global__ __launch_bounds__(256) void k_precompute(int layer, int do_update) {
    extern __shared__ unsigned dyn[];
    unsigned* sA = dyn;                       // 128*36
    unsigned* sW = dyn + 128 * 36;            // 192*36 hi only
    int tid = threadIdx.x, n0 = blockIdx.x * 128;
    int warp = tid >> 5, lane = tid & 31;
    int wm = warp >> 1, wn = warp & 1;
    int gid = lane >> 2, tig = lane & 3;
    if (blockIdx.x == 0 && tid < 128) g_stats[tid] = 0.0;

    {
        const uint4* src = reinterpret_cast<const uint4*>(g_wpre[layer]);
        uint4* dst = reinterpret_cast<uint4*>(sW);
        for (int idx = tid; idx < 192 * 36 / 4; idx += 256) dst[idx] = src[idx];
    }
    for (int idx = tid; idx < 128 * 32; idx += 256) {
        int nr = idx >> 5, cw = idx & 31;
        int n = n0 + nr;
        if (n < NN) {
            size_t off = (size_t)n * 64 + cw * 2;
            float2 h = *reinterpret_cast<const float2*>(&g_h[off]);
            if (do_update) {
                float2 hn = *reinterpret_cast<const float2*>(&g_hnew[off]);
                int j = cw * 2;
                h.x = sp_f(hn.x * g_ab[j]     + g_ab[64 + j])     + h.x;
                h.y = sp_f(hn.y * g_ab[j + 1] + g_ab[64 + j + 1]) + h.y;
                *reinterpret_cast<float2*>(&g_h[off]) = h;
            }
            sA[nr * 36 + cw] = pack2(h.x, h.y);
            *reinterpret_cast<float2*>(&g_hnew[off]) = make_float2(0.f, 0.f);
        } else sA[nr * 36 + cw] = 0u;
    }
    __syncthreads();

    float acc[2][12][4];
#pragma unroll
    for (int mt = 0; mt < 2; mt++)
#pragma unroll
        for (int nt = 0; nt < 12; nt++) {
            int nc = wn * 96 + nt * 8 + tig * 2;
            float2 bv = *reinterpret_cast<const float2*>(&g_bpre[layer][nc]);
            acc[mt][nt][0] = bv.x; acc[mt][nt][1] = bv.y;
            acc[mt][nt][2] = bv.x; acc[mt][nt][3] = bv.y;
        }
    mma_tiles_hi<4, 12, 36>(sA, sW, acc, wm, wn * 96, gid, tig);
#pragma unroll
    for (int mt = 0; mt < 2; mt++)
#pragma unroll
        for (int nt = 0; nt < 12; nt++) {
            int nc = wn * 96 + nt * 8 + tig * 2;
            unsigned* O = nc < 64 ? g_Arh : (nc < 128 ? g_Ach : g_Brh);
            int cw = (nc & 63) >> 1;
            int row = wm * 32 + mt * 16 + gid;
            int n = n0 + row;
            if (n < NN)     O[(size_t)n * 32 + cw]       = pack2(acc[mt][nt][0], acc[mt][nt][1]);
            if (n + 8 < NN) O[(size_t)(n + 8) * 32 + cw] = pack2(acc[mt][nt][2], acc[mt][nt][3]);
        }
}

// ------------------------------------------------------------------ fused edge pipeline
// R13 config but with PAIR-scoped named barriers: warp pair wm owns sA rows
// [wm*32, wm*32+32) and its sRow/sCol entries end-to-end.
__global__ __launch_bounds__(256, 3) void k_edge(const int* eidx, int layer,
                                                 const float* b2, const float* b4,
                                                 int store_ea) {
    extern __shared__ unsigned dyn[];
    unsigned* sA = dyn;                    // 128*36
    unsigned* sW = dyn + 128 * 36;         // 4 stages * 2304
    __shared__ float sB2[64], sB4[64];
    __shared__ int sRow[128], sCol[128];

    int tid = threadIdx.x;
    int warp = tid >> 5, lane = tid & 31;
    int wm = warp >> 1, wn = warp & 1;
    int gid = lane >> 2, tig = lane & 3;
    int ptid = (wn << 5) | lane;           // 0..63 within pair

    if (tid < 64) { sB2[tid] = b2[tid]; sB4[tid] = b4[tid]; }
    {
        const uint4* src = reinterpret_cast<const uint4*>(&g_wehi[layer][0][0]);
        uint4* dst = reinterpret_cast<uint4*>(sW);
        for (int idx = tid; idx < 4 * 2304 / 4; idx += 256) dst[idx] = src[idx];
    }
    const unsigned* W1h = sW;
    const unsigned* W2h = sW + 2304;
    const unsigned* W3h = sW + 4608;
    const unsigned* W4h = sW + 6912;
    __syncthreads();                       // weights + biases ready (once)

    for (int t = blockIdx.x; t < NT_EDGE; t += gridDim.x) {
        int e0 = t * 128;
        pair_bar(wm);                      // prior tile stage-4 reads done (pair)
        if (ptid < 32) {
            int r = wm * 32 + ptid;
            int e = e0 + r; if (e >= EE) e = EE - 1;
            sRow[r] = clampi(eidx[e], NN);
            sCol[r] = clampi(eidx[EE + e], NN);
        }
        for (int idx = ptid; idx < 32 * 32; idx += 64) {
            int er = wm * 32 + (idx >> 5), cw = idx & 31;
            int e = e0 + er; if (e >= EE) e = EE - 1;
            sA[er * 36 + cw] = g_ea[(size_t)e * 32 + cw];
        }
        pair_bar(wm);

        float acc[2][4][4];

        // ---- stage 1: t = sp(sA @ W1c + Ar[row] + Ac[col])
#pragma unroll
        for (int mt = 0; mt < 2; mt++)
#pragma unroll
            for (int nt = 0; nt < 4; nt++) {
                int row = wm * 32 + mt * 16 + gid;
                int cw = wn * 16 + nt * 4 + tig;
                float2 a0 = up2(g_Arh[(size_t)sRow[row] * 32 + cw]);
                float2 q0 = up2(g_Ach[(size_t)sCol[row] * 32 + cw]);
                float2 a1 = up2(g_Arh[(size_t)sRow[row + 8] * 32 + cw]);
                float2 q1 = up2(g_Ach[(size_t)sCol[row + 8] * 32 + cw]);
                acc[mt][nt][0] = a0.x + q0.x; acc[mt][nt][1] = a0.y + q0.y;
                acc[mt][nt][2] = a1.x + q1.x; acc[mt][nt][3] = a1.y + q1.y;
            }
        mma_tiles_hi<4, 4, 36>(sA, W1h, acc, wm, wn * 32, gid, tig);
        pair_bar(wm);
#pragma unroll
        for (int mt = 0; mt < 2; mt++)
#pragma unroll
            for (int nt = 0; nt < 4; nt++) {
                int row = wm * 32 + mt * 16 + gid;
                int cw = wn * 16 + nt * 4 + tig;
                sA[row * 36 + cw]       = pack2(sp_f(acc[mt][nt][0]), sp_f(acc[mt][nt][1]));
                sA[(row + 8) * 36 + cw] = pack2(sp_f(acc[mt][nt][2]), sp_f(acc[mt][nt][3]));
            }
        pair_bar(wm);

        // ---- stage 2: ea_new = sA @ W2 + b2
#pragma unroll
        for (int mt = 0; mt < 2; mt++)
#pragma unroll
            for (int nt = 0; nt < 4; nt++) {
                int col = wn * 32 + nt * 8 + tig * 2;
                float2 bv = *reinterpret_cast<const float2*>(&sB2[col]);
                acc[mt][nt][0] = bv.x; acc[mt][nt][1] = bv.y;
                acc[mt][nt][2] = bv.x; acc[mt][nt][3] = bv.y;
            }
        mma_tiles_hi<4, 4, 36>(sA, W2h, acc, wm, wn * 32, gid, tig);
        pair_bar(wm);
#pragma unroll
        for (int mt = 0; mt < 2; mt++)
#pragma unroll
            for (int nt = 0; nt < 4; nt++) {
                int row = wm * 32 + mt * 16 + gid;
                int cw = wn * 16 + nt * 4 + tig;
                unsigned p0 = pack2(acc[mt][nt][0], acc[mt][nt][1]);
                unsigned p1 = pack2(acc[mt][nt][2], acc[mt][nt][3]);
                sA[row * 36 + cw]       = p0;
                sA[(row + 8) * 36 + cw] = p1;
                if (store_ea) {
                    int e = e0 + row;
                    if (e < EE)     g_ea[(size_t)e * 32 + cw]       = p0;
                    if (e + 8 < EE) g_ea[(size_t)(e + 8) * 32 + cw] = p1;
                }
            }
        pair_bar(wm);

        // ---- stage 3: u = sp(sA @ W3 + Br[row])
#pragma unroll
        for (int mt = 0; mt < 2; mt++)
#pragma unroll
            for (int nt = 0; nt < 4; nt++) {
                int row = wm * 32 + mt * 16 + gid;
                int cw = wn * 16 + nt * 4 + tig;
                float2 v0 = up2(g_Brh[(size_t)sRow[row] * 32 + cw]);
                float2 v1 = up2(g_Brh[(size_t)sRow[row + 8] * 32 + cw]);
                acc[mt][nt][0] = v0.x; acc[mt][nt][1] = v0.y;
                acc[mt][nt][2] = v1.x; acc[mt][nt][3] = v1.y;
            }
        mma_tiles_hi<4, 4, 36>(sA, W3h, acc, wm, wn * 32, gid, tig);
        pair_bar(wm);
#pragma unroll
        for (int mt = 0; mt < 2; mt++)
#pragma unroll
            for (int nt = 0; nt < 4; nt++) {
                int row = wm * 32 + mt * 16 + gid;
                int cw = wn * 16 + nt * 4 + tig;
                sA[row * 36 + cw]       = pack2(sp_f(acc[mt][nt][0]), sp_f(acc[mt][nt][1]));
                sA[(row + 8) * 36 + cw] = pack2(sp_f(acc[mt][nt][2]), sp_f(acc[mt][nt][3]));
            }
        pair_bar(wm);

        // ---- stage 4: msg = sA @ W4 + b4 -> red scatter (no trailing bar;
        //      loop-top pair_bar protects next-tile rewrite)
#pragma unroll
        for (int mt = 0; mt < 2; mt++)
#pragma unroll
            for (int nt = 0; nt < 4; nt++) {
                int col = wn * 32 + nt * 8 + tig * 2;
                float2 bv = *reinterpret_cast<const float2*>(&sB4[col]);
                acc[mt][nt][0] = bv.x; acc[mt][nt][1] = bv.y;
                acc[mt][nt][2] = bv.x; acc[mt][nt][3] = bv.y;
            }
        mma_tiles_hi<4, 4, 36>(sA, W4h, acc, wm, wn * 32, gid, tig);
#pragma unroll
        for (int mt = 0; mt < 2; mt++)
#pragma unroll
            for (int nt = 0; nt < 4; nt++) {
                int row = wm * 32 + mt * 16 + gid;
                int col = wn * 32 + nt * 8 + tig * 2;
                int e = e0 + row;
                if (e < EE)
                    red2(&g_hnew[(size_t)sCol[row] * 64 + col], acc[mt][nt][0], acc[mt][nt][1]);
                if (e + 8 < EE)
                    red2(&g_hnew[(size_t)sCol[row + 8] * 64 + col], acc[mt][nt][2], acc[mt][nt][3]);
            }
    }
}

// ------------------------------------------------------------------ tail kernels
__global__ void k_stats() {
    int c = threadIdx.x & 63, rr = threadIdx.x >> 6;
    double s = 0.0, s2 = 0.0;
    for (int n = blockIdx.x * 4 + rr; n < NN; n += gridDim.x * 4) {
        float v = g_hnew[n * 64 + c];
        s += v; s2 += (double)v * v;
    }
    __shared__ double sh[8][64];
    sh[rr][c] = s; sh[4 + rr][c] = s2;
    __syncthreads();
    if (rr == 0) {
        atomicAdd(&g_stats[c],      sh[0][c] + sh[1][c] + sh[2][c] + sh[3][c]);
        atomicAdd(&g_stats[64 + c], sh[4][c] + sh[5][c] + sh[6][c] + sh[7][c]);
    }
}

__global__ void k_finalize(const float* gamma, const float* beta) {
    int j = threadIdx.x;
    double mu = g_stats[j] / (double)NN;
    double var = g_stats[64 + j] / (double)NN - mu * mu;
    float a = rsqrtf((float)var + 1e-5f) * gamma[j];
    g_ab[j] = a;
    g_ab[64 + j] = beta[j] - (float)mu * a;
}

__global__ void k_update_pool(const int* batch) {
    int idx = blockIdx.x * 256 + threadIdx.x;
    int j = idx & 63;
    float v = g_hnew[idx] * g_ab[j] + g_ab[64 + j];
    float h = sp_f(v) + g_h[idx];
    int b = clampi(batch[idx >> 6], GG);
    atomicAdd(&g_pool[b * 64 + j], h);
    if (j == 0) atomicAdd(&g_cnt[b], 1.f);
}

__global__ void k_predict(const float* W1, const float* b1,
                          const float* W2, const float* b2,
                          const float* W3, const float* b3, float* out) {
    __shared__ float gr[64], z1[128], z2[128];
    __shared__ float red[4];
    int g = blockIdx.x, t = threadIdx.x;
    if (t < 64) gr[t] = g_pool[g * 64 + t] / fmaxf(g_cnt[g], 1.f);
    __syncthreads();
    float acc = b1[t];
    for (int k = 0; k < 64; k++) acc = fmaf(gr[k], W1[k * 128 + t], acc);
    z1[t] = sp_f(acc);
    __syncthreads();
    acc = b2[t];
    for (int k = 0; k < 128; k++) acc = fmaf(z1[k], W2[k * 128 + t], acc);
    z2[t] = sp_f(acc);
    __syncthreads();
    float v = z2[t] * W3[t];
    for (int o = 16; o > 0; o >>= 1) v += __shfl_down_sync(0xffffffff, v, o);
    if ((t & 31) == 0) red[t >> 5] = v;
    __syncthreads();
    if (t == 0) out[g] = red[0] + red[1] + red[2] + red[3] + b3[0];
}

// ------------------------------------------------------------------ launch
extern "C" void kernel_launch(void* const* d_in, const int* in_sizes, int n_in,
                              void* d_out, int out_size) {
    const float* x         = (const float*)d_in[0];
    const float* edge_attr = (const float*)d_in[1];
    const float* charge    = (const float*)d_in[2];
    const int*   eidx      = (const int*)d_in[3];
    const int*   batch     = (const int*)d_in[4];
    const float* W_charge  = (const float*)d_in[5];
    const float* b_charge  = (const float*)d_in[6];
    const float* W_atom    = (const float*)d_in[7];
    const float* b_atom    = (const float*)d_in[8];
    const float* W_bond    = (const float*)d_in[9];
    const float* b_bond    = (const float*)d_in[10];
    const float* nu_W1     = (const float*)d_in[11];
    const float* nu_b1     = (const float*)d_in[12];
    const float* nu_W2     = (const float*)d_in[13];
    const float* nu_b2     = (const float*)d_in[14];
    const float* eu_W1     = (const float*)d_in[15];
    const float* eu_b1     = (const float*)d_in[16];
    const float* eu_W2     = (const float*)d_in[17];
    const float* eu_b2     = (const float*)d_in[18];
    const float* bn_g      = (const float*)d_in[19];
    const float* bn_b      = (const float*)d_in[20];
    const float* p_W1      = (const float*)d_in[21];
    const float* p_b1      = (const float*)d_in[22];
    const float* p_W2      = (const float*)d_in[23];
    const float* p_b2      = (const float*)d_in[24];
    const float* p_W3      = (const float*)d_in[25];
    const float* p_b3      = (const float*)d_in[26];
    float* out = (float*)d_out;

    const int PRE_SMEM  = (128 * 36 + 192 * 36) * 4;           // 46080
    const int EDGE_SMEM = (128 * 36 + 4 * 2304) * 4;           // 55296
    const int EN_SMEM   = (128 * 68 + 2 * 64 * 68) * 4;        // 69632
    const int EB_SMEM   = (5248 + 128 * 36 + 64 * 36) * 4;     // 48640
    cudaFuncSetAttribute(k_precompute, cudaFuncAttributeMaxDynamicSharedMemorySize, PRE_SMEM);
    cudaFuncSetAttribute(k_edge, cudaFuncAttributeMaxDynamicSharedMemorySize, EDGE_SMEM);
    cudaFuncSetAttribute(k_embed_nodes_mma, cudaFuncAttributeMaxDynamicSharedMemorySize, EN_SMEM);
    cudaFuncSetAttribute(k_embed_edges_mma, cudaFuncAttributeMaxDynamicSharedMemorySize, EB_SMEM);

    k_charge<<<64, 256>>>(charge, W_charge, b_charge);
    k_cvt_all<<<23, 256>>>(eu_W1, eu_b1, nu_W1, nu_b1, eu_W2, nu_W2, W_bond, W_atom);
    k_embed_nodes_mma<<<(NN + 127) / 128, 256, EN_SMEM>>>(x, batch, b_atom);
    k_embed_edges_mma<<<NT_EDGE, 256, EB_SMEM>>>(edge_attr, b_bond);

    for (int i = 0; i < LL; i++) {
        k_precompute<<<(NN + 127) / 128, 256, PRE_SMEM>>>(i, i > 0 ? 1 : 0);
        k_edge<<<444, 256, EDGE_SMEM>>>(eidx, i, eu_b2 + i * 64, nu_b2 + i * 64,
                                        i < LL - 1 ? 1 : 0);
        k_stats<<<256, 256>>>();
        k_finalize<<<1, 64>>>(bn_g + i * 64, bn_b + i * 64);
    }
    k_update_pool<<<(NN * DD) / 256, 256>>>(batch);
    k_predict<<<GG, 128>>>(p_W1, p_b1, p_W2, p_b2, p_W3, p_b3, out);
}